// round 12
// baseline (speedup 1.0000x reference)
#include <cuda_runtime.h>
#include <cuda_fp16.h>
#include <math.h>
#include <stdint.h>

#define TT 2048
#define HIDD 2048
#define NH 32
#define DH 64
#define KD 2048
#define NE (2048u*2048u)

// fp32 scratch: q,k,v,g, qc,kc,vc, o_scan + alpha/beta
__device__ __align__(16) float g_scratch[8ull*NE + 2ull*TT*NH];
// fp16 scratch: xh, wqh, wkh, wvh, wgh, woh, oh   (wqh..wgh contiguous!)
__device__ __align__(16) __half g_half[7ull*NE];

#define OFF_Q  (0ull*NE)
#define OFF_K  (1ull*NE)
#define OFF_V  (2ull*NE)
#define OFF_G  (3ull*NE)
#define OFF_QC (4ull*NE)
#define OFF_KC (5ull*NE)
#define OFF_VC (6ull*NE)
#define OFF_O  (7ull*NE)
#define OFF_AL (8ull*NE)
#define OFF_BE (8ull*NE + (unsigned long long)TT*NH)

#define HOFF_X  (0ull*NE)
#define HOFF_WQ (1ull*NE)
#define HOFF_WK (2ull*NE)
#define HOFF_WV (3ull*NE)
#define HOFF_WG (4ull*NE)
#define HOFF_WO (5ull*NE)
#define HOFF_O  (6ull*NE)

typedef unsigned long long u64;

// ---------------------------------------------------------------------------
// FP16 tensor-core NT GEMM: C[m,n] = sum_k A[m*K+k]*B[n*K+k], fp32 accum.
// Block 128x128, BK=32 halves, 8 warps (4m x 2n) of 32x64, mma.m16n8k16.
// SPLIT=true: bx spans 4 concatenated weight/output regions (projection fuse).
// ---------------------------------------------------------------------------
#define GK 2048
#define HTILE_BYTES (128*80)          // 10240 per matrix
#define HSTG (2*HTILE_BYTES)          // 20480 per stage (A+B)
#define GEMM_SMEM (2u*HSTG)           // 40960, double buffered

__device__ __forceinline__ void cp_async16(uint32_t saddr, const void* gptr) {
    asm volatile("cp.async.ca.shared.global [%0], [%1], 16;\n" :: "r"(saddr), "l"(gptr));
}

__device__ __forceinline__ void ldsm4(uint32_t* r, uint32_t addr) {
    asm volatile("ldmatrix.sync.aligned.m8n8.x4.shared.b16 {%0,%1,%2,%3}, [%4];"
                 : "=r"(r[0]), "=r"(r[1]), "=r"(r[2]), "=r"(r[3]) : "r"(addr));
}

__device__ __forceinline__ void mma16(float* c, const uint32_t* a, const uint32_t* b) {
    asm volatile(
        "mma.sync.aligned.m16n8k16.row.col.f32.f16.f16.f32 "
        "{%0,%1,%2,%3},{%4,%5,%6,%7},{%8,%9},{%0,%1,%2,%3};\n"
        : "+f"(c[0]), "+f"(c[1]), "+f"(c[2]), "+f"(c[3])
        : "r"(a[0]), "r"(a[1]), "r"(a[2]), "r"(a[3]), "r"(b[0]), "r"(b[1]));
}

template<bool SPLIT>
__global__ __launch_bounds__(256, 2) void gemm_f16(const __half* __restrict__ A,
                                                   const __half* __restrict__ B,
                                                   float* __restrict__ C) {
    extern __shared__ char dsm[];
    const int tid = threadIdx.x;
    const int warp = tid >> 5, lane = tid & 31;
    const int grp = lane >> 2, tig = lane & 3;
    const int wm = (warp >> 1) * 32, wn = (warp & 1) * 64;
    const int bx = blockIdx.x, by = blockIdx.y;

    const __half* Ag = A + (size_t)(by * 128) * GK;
    const __half* Bg = B + (size_t)(bx * 128) * GK;   // weights contiguous across regions

    float* Cb;
    int gnb;
    if (SPLIT) {
        Cb = C + (size_t)(bx >> 4) * NE;
        gnb = (bx & 15) * 128;
    } else {
        Cb = C;
        gnb = bx * 128;
    }

    float c[2][8][4];
#pragma unroll
    for (int mi = 0; mi < 2; mi++)
#pragma unroll
        for (int nj = 0; nj < 8; nj++)
#pragma unroll
            for (int r = 0; r < 4; r++) c[mi][nj][r] = 0.f;

    const uint32_t smbase = (uint32_t)__cvta_generic_to_shared(dsm);
    const int NKI = GK / 32;

    const int a_r  = (lane & 7) + ((lane >> 3) & 1) * 8;
    const int a_c8 = ((lane >> 4) & 1) * 8;
    const int b_r  = (lane & 7) + ((lane >> 4) & 1) * 8;
    const int b_c8 = ((lane >> 3) & 1) * 8;

    // 128 rows * 4 chunks(16B) = 512 chunks per matrix; 256 threads -> 2 iters
    auto issue = [&](int s, int kt) {
        uint32_t stA = smbase + (uint32_t)(s * HSTG);
        uint32_t stB = stA + HTILE_BYTES;
#pragma unroll
        for (int i = 0; i < 2; i++) {
            int idx = tid + i * 256;      // 0..511
            int r = idx >> 2, ch = idx & 3;
            cp_async16(stA + (uint32_t)(r * 80 + ch * 16),
                       Ag + (size_t)r * GK + kt * 32 + ch * 8);
            cp_async16(stB + (uint32_t)(r * 80 + ch * 16),
                       Bg + (size_t)r * GK + kt * 32 + ch * 8);
        }
        asm volatile("cp.async.commit_group;\n");
    };

    issue(0, 0);

    for (int kt = 0; kt < NKI; kt++) {
        const int s = kt & 1;
        if (kt + 1 < NKI) {
            issue((kt + 1) & 1, kt + 1);
            asm volatile("cp.async.wait_group 1;\n");
        } else {
            asm volatile("cp.async.wait_group 0;\n");
        }
        __syncthreads();

        uint32_t stA = smbase + (uint32_t)(s * HSTG);
        uint32_t stB = stA + HTILE_BYTES;

#pragma unroll
        for (int ks = 0; ks < 2; ks++) {
            uint32_t av[2][4], bv[8][2];
#pragma unroll
            for (int mi = 0; mi < 2; mi++) {
                uint32_t addr = stA + (uint32_t)((wm + mi * 16 + a_r) * 80
                                                 + (ks * 16 + a_c8) * 2);
                ldsm4(av[mi], addr);
            }
#pragma unroll
            for (int njp = 0; njp < 4; njp++) {
                uint32_t r4[4];
                uint32_t addr = stB + (uint32_t)((wn + njp * 16 + b_r) * 80
                                                 + (ks * 16 + b_c8) * 2);
                ldsm4(r4, addr);
                bv[njp * 2][0] = r4[0]; bv[njp * 2][1] = r4[1];
                bv[njp * 2 + 1][0] = r4[2]; bv[njp * 2 + 1][1] = r4[3];
            }
#pragma unroll
            for (int mi = 0; mi < 2; mi++)
#pragma unroll
                for (int nj = 0; nj < 8; nj++)
                    mma16(c[mi][nj], av[mi], bv[nj]);
        }
        __syncthreads();
    }

#pragma unroll
    for (int mi = 0; mi < 2; mi++) {
        const int gm = by * 128 + wm + mi * 16 + grp;
#pragma unroll
        for (int nj = 0; nj < 8; nj++) {
            const int gn = gnb + wn + nj * 8 + 2 * tig;
            *(float2*)(Cb + (size_t)gm * 2048 + gn) = make_float2(c[mi][nj][0], c[mi][nj][1]);
            *(float2*)(Cb + (size_t)(gm + 8) * 2048 + gn) = make_float2(c[mi][nj][2], c[mi][nj][3]);
        }
    }
}

// ---------------------------------------------------------------------------
// fp32 -> fp16 conversion of x + 5 weight matrices.
// ---------------------------------------------------------------------------
__global__ __launch_bounds__(256) void to_half(const float* __restrict__ s0, __half* __restrict__ d0,
                                               const float* __restrict__ s1, __half* __restrict__ d1,
                                               const float* __restrict__ s2, __half* __restrict__ d2,
                                               const float* __restrict__ s3, __half* __restrict__ d3,
                                               const float* __restrict__ s4, __half* __restrict__ d4,
                                               const float* __restrict__ s5, __half* __restrict__ d5) {
    const float* s; __half* d;
    switch (blockIdx.y) {
        case 0: s = s0; d = d0; break;
        case 1: s = s1; d = d1; break;
        case 2: s = s2; d = d2; break;
        case 3: s = s3; d = d3; break;
        case 4: s = s4; d = d4; break;
        default: s = s5; d = d5; break;
    }
    unsigned i = blockIdx.x * 256u + threadIdx.x;
    float4 v = ((const float4*)s)[i];
    __half2 lo = __floats2half2_rn(v.x, v.y);
    __half2 hi = __floats2half2_rn(v.z, v.w);
    ((__half2*)d)[2 * i] = lo;
    ((__half2*)d)[2 * i + 1] = hi;
}

// ---------------------------------------------------------------------------
// Causal depthwise conv (K=4) + SiLU. blockIdx.y selects q/k/v.
// ---------------------------------------------------------------------------
__global__ __launch_bounds__(256) void conv_silu(const float* __restrict__ in0,
                                                 const float* __restrict__ w0,
                                                 const float* __restrict__ b0,
                                                 float* __restrict__ out0,
                                                 const float* __restrict__ in1,
                                                 const float* __restrict__ w1,
                                                 const float* __restrict__ b1,
                                                 float* __restrict__ out1,
                                                 const float* __restrict__ in2,
                                                 const float* __restrict__ w2,
                                                 const float* __restrict__ b2,
                                                 float* __restrict__ out2) {
    const float *in, *w, *b; float* out;
    switch (blockIdx.y) {
        case 0: in = in0; w = w0; b = b0; out = out0; break;
        case 1: in = in1; w = w1; b = b1; out = out1; break;
        default: in = in2; w = w2; b = b2; out = out2; break;
    }
    unsigned idx = blockIdx.x * 256u + threadIdx.x;
    int c = idx & (KD - 1);
    int t = idx >> 11;
    float4 w4 = ((const float4*)w)[c];
    float y = b[c];
    int ts = t - 3;
    if (ts >= 0)     y += in[(size_t)ts * KD + c] * w4.x;
    if (ts + 1 >= 0) y += in[(size_t)(ts + 1) * KD + c] * w4.y;
    if (ts + 2 >= 0) y += in[(size_t)(ts + 2) * KD + c] * w4.z;
    y += in[(size_t)t * KD + c] * w4.w;
    out[idx] = y / (1.f + expf(-y));
}

// ---------------------------------------------------------------------------
// beta/alpha via tiled fp32 mini-GEMM (exact fp32; feeds the scan).
// ---------------------------------------------------------------------------
__global__ __launch_bounds__(256) void bproj(const float* __restrict__ x,
                                             const float* __restrict__ Wb,
                                             const float* __restrict__ bb,
                                             const float* __restrict__ Wgk,
                                             const float* __restrict__ bgk,
                                             const float* __restrict__ A_log,
                                             const float* __restrict__ dt_bias,
                                             float* __restrict__ alpha,
                                             float* __restrict__ beta) {
    __shared__ __align__(16) float xs[32][33];
    __shared__ __align__(16) float ws[64][33];
    const int tid = threadIdx.x;
    const int t0 = blockIdx.x * 32;
    const int tn = tid & 15, tt = tid >> 4;
    const int tr = (tt & 15) * 2;
    const int nc = tn * 4;

    float acc[2][4];
#pragma unroll
    for (int i = 0; i < 2; i++)
#pragma unroll
        for (int j = 0; j < 4; j++) acc[i][j] = 0.f;

    for (int k0 = 0; k0 < HIDD; k0 += 32) {
        {
            int row = tid >> 3, kc = (tid & 7) * 4;
            float4 v4 = *(const float4*)&x[(size_t)(t0 + row) * HIDD + k0 + kc];
            xs[row][kc] = v4.x; xs[row][kc + 1] = v4.y;
            xs[row][kc + 2] = v4.z; xs[row][kc + 3] = v4.w;
        }
#pragma unroll
        for (int r = 0; r < 2; r++) {
            int idx = tid + r * 256;
            int n = idx >> 3, kc = (idx & 7) * 4;
            const float* src = (n < 32) ? &Wb[(size_t)n * HIDD + k0 + kc]
                                        : &Wgk[(size_t)(n - 32) * HIDD + k0 + kc];
            float4 v4 = *(const float4*)src;
            ws[n][kc] = v4.x; ws[n][kc + 1] = v4.y;
            ws[n][kc + 2] = v4.z; ws[n][kc + 3] = v4.w;
        }
        __syncthreads();
#pragma unroll
        for (int kk = 0; kk < 32; kk++) {
            float xa0 = xs[tr][kk], xa1 = xs[tr + 1][kk];
            float w0 = ws[nc][kk], w1 = ws[nc + 1][kk];
            float w2 = ws[nc + 2][kk], w3 = ws[nc + 3][kk];
            acc[0][0] += xa0 * w0; acc[0][1] += xa0 * w1;
            acc[0][2] += xa0 * w2; acc[0][3] += xa0 * w3;
            acc[1][0] += xa1 * w0; acc[1][1] += xa1 * w1;
            acc[1][2] += xa1 * w2; acc[1][3] += xa1 * w3;
        }
        __syncthreads();
    }

#pragma unroll
    for (int i = 0; i < 2; i++) {
        int t = t0 + tr + i;
#pragma unroll
        for (int j = 0; j < 4; j++) {
            int n = nc + j;
            if (n < 32) {
                beta[t * NH + n] = 1.f / (1.f + expf(-(acc[i][j] + bb[n])));
            } else {
                int h = n - 32;
                float z = acc[i][j] + bgk[h] + dt_bias[h];
                float sp = fmaxf(z, 0.f) + log1pf(expf(-fabsf(z)));
                alpha[t * NH + h] = expf(-expf(A_log[h]) * sp);
            }
        }
    }
}

// ---------------------------------------------------------------------------
// YaRN RoPE + l2norm, in-place.
// ---------------------------------------------------------------------------
__global__ __launch_bounds__(128) void rope_l2norm(float* __restrict__ q,
                                                   float* __restrict__ k) {
    int gw = blockIdx.x * 4 + (threadIdx.x >> 5);
    int lane = threadIdx.x & 31;
    int t = gw >> 5;
    int h = gw & 31;
    float* base = (blockIdx.y == 0 ? q : k) + (size_t)t * KD + h * DH;

    int m = (2 * lane) & 31;
    double invf = pow(10000.0, -((double)(2 * m) / 64.0));
    double wl = 6.283185307179586 / invf;
    double ramp = (wl - 1.0) / 31.0;
    ramp = ramp < 0.0 ? 0.0 : (ramp > 1.0 ? 1.0 : ramp);
    double scale = 1.0 + 31.0 * ramp;
    float f = (float)(((double)t / scale) * invf);
    float s, c;
    sincosf(f, &s, &c);

    float x1 = base[2 * lane];
    float x2 = base[2 * lane + 1];
    __syncwarp();
    float lo = x1 * c - x2 * s;
    float hi = x1 * s + x2 * c;
    float ss = lo * lo + hi * hi;
#pragma unroll
    for (int off = 16; off; off >>= 1) ss += __shfl_xor_sync(0xffffffffu, ss, off);
    float r = rsqrtf(ss + 1e-6f);
    base[lane] = lo * r;
    base[lane + 32] = hi * r;
}

// ---------------------------------------------------------------------------
// Sequential delta-rule scan (packed f32x2), COLUMN-SPLIT:
// recurrence is independent per v-column j. 64 blocks = (head, col-half).
// 128 threads: thread owns 16 rows (8 u64) of one column; 4-lane reduce.
// ---------------------------------------------------------------------------
__device__ __forceinline__ u64 pk2(float lo, float hi) {
    u64 r; asm("mov.b64 %0,{%1,%2};" : "=l"(r) : "f"(lo), "f"(hi)); return r;
}
__device__ __forceinline__ void up2(u64 v, float& lo, float& hi) {
    asm("mov.b64 {%0,%1},%2;" : "=f"(lo), "=f"(hi) : "l"(v));
}
__device__ __forceinline__ u64 fma2(u64 a, u64 b, u64 c) {
    u64 d; asm("fma.rn.f32x2 %0,%1,%2,%3;" : "=l"(d) : "l"(a), "l"(b), "l"(c)); return d;
}
__device__ __forceinline__ u64 mul2(u64 a, u64 b) {
    u64 d; asm("mul.rn.f32x2 %0,%1,%2;" : "=l"(d) : "l"(a), "l"(b)); return d;
}

#define CH 32
__global__ __launch_bounds__(128) void scan_kernel(const float* __restrict__ q,
                                                   const float* __restrict__ k,
                                                   const float* __restrict__ v,
                                                   const float* __restrict__ alpha,
                                                   const float* __restrict__ beta,
                                                   float* __restrict__ o) {
    int h  = blockIdx.x >> 1;
    int cb = (blockIdx.x & 1) * 32;    // column base within head
    __shared__ __align__(16) float sq[CH][DH];
    __shared__ __align__(16) float sk[CH][DH];
    __shared__ __align__(16) float sv[CH][32];
    __shared__ __align__(16) float so[CH][32];
    __shared__ float sa[CH], sb2[CH];

    int tid = threadIdx.x;
    int jl = tid >> 2;                 // 0..31 local column
    int qt = tid & 3;                  // quarter: rows [qt*16, qt*16+16)
    int rbase = qt * 16;

    u64 S2[8];
#pragma unroll
    for (int i = 0; i < 8; i++) S2[i] = 0ull;

    for (int t0 = 0; t0 < TT; t0 += CH) {
        // q,k full 64 dims: 512 float4 each
#pragma unroll
        for (int r = 0; r < 4; r++) {
            int fi = tid + r * 128;
            int s = fi >> 4;
            int d4 = fi & 15;
            size_t gidx = (size_t)(t0 + s) * KD + h * DH + d4 * 4;
            ((float4*)sq[s])[d4] = *(const float4*)&q[gidx];
            ((float4*)sk[s])[d4] = *(const float4*)&k[gidx];
        }
        // v: only our 32 columns: 256 float4
#pragma unroll
        for (int r = 0; r < 2; r++) {
            int fi = tid + r * 128;
            int s = fi >> 3;
            int c4 = fi & 7;
            ((float4*)sv[s])[c4] =
                *(const float4*)&v[(size_t)(t0 + s) * KD + h * DH + cb + c4 * 4];
        }
        if (tid < CH) {
            sa[tid]  = alpha[(t0 + tid) * NH + h];
            sb2[tid] = beta[(t0 + tid) * NH + h];
        }
        __syncthreads();

        for (int s = 0; s < CH; s++) {
            const u64* k2 = (const u64*)&sk[s][rbase];
            const u64* q2 = (const u64*)&sq[s][rbase];
            u64 e0 = 0ull, e1 = 0ull, e2 = 0ull, e3 = 0ull;
#pragma unroll
            for (int ii = 0; ii < 8; ii += 4) {
                e0 = fma2(k2[ii],     S2[ii],     e0);
                e1 = fma2(k2[ii + 1], S2[ii + 1], e1);
                e2 = fma2(k2[ii + 2], S2[ii + 2], e2);
                e3 = fma2(k2[ii + 3], S2[ii + 3], e3);
            }
            float l0, h0, l1, h1, l2, h2, l3, h3;
            up2(e0, l0, h0); up2(e1, l1, h1); up2(e2, l2, h2); up2(e3, l3, h3);
            float errdot = ((l0 + h0) + (l1 + h1)) + ((l2 + h2) + (l3 + h3));
            errdot += __shfl_xor_sync(0xffffffffu, errdot, 1);
            errdot += __shfl_xor_sync(0xffffffffu, errdot, 2);
            float a = sa[s];
            float u = sb2[s] * (sv[s][jl] - a * errdot);
            u64 ab = pk2(a, a), ub = pk2(u, u);
            u64 o0 = 0ull, o1 = 0ull, o2 = 0ull, o3 = 0ull;
#pragma unroll
            for (int ii = 0; ii < 8; ii += 4) {
                S2[ii]     = fma2(k2[ii],     ub, mul2(ab, S2[ii]));
                S2[ii + 1] = fma2(k2[ii + 1], ub, mul2(ab, S2[ii + 1]));
                S2[ii + 2] = fma2(k2[ii + 2], ub, mul2(ab, S2[ii + 2]));
                S2[ii + 3] = fma2(k2[ii + 3], ub, mul2(ab, S2[ii + 3]));
                o0 = fma2(q2[ii],     S2[ii],     o0);
                o1 = fma2(q2[ii + 1], S2[ii + 1], o1);
                o2 = fma2(q2[ii + 2], S2[ii + 2], o2);
                o3 = fma2(q2[ii + 3], S2[ii + 3], o3);
            }
            up2(o0, l0, h0); up2(o1, l1, h1); up2(o2, l2, h2); up2(o3, l3, h3);
            float ov = ((l0 + h0) + (l1 + h1)) + ((l2 + h2) + (l3 + h3));
            ov += __shfl_xor_sync(0xffffffffu, ov, 1);
            ov += __shfl_xor_sync(0xffffffffu, ov, 2);
            if (qt == 0) so[s][jl] = ov;
        }
        __syncthreads();
#pragma unroll
        for (int r = 0; r < 2; r++) {
            int fi = tid + r * 128;
            int s = fi >> 3;
            int c4 = fi & 7;
            *(float4*)&o[(size_t)(t0 + s) * KD + h * DH + cb + c4 * 4] =
                ((float4*)so[s])[c4];
        }
    }
}

// ---------------------------------------------------------------------------
// Epilogue: o = o_scan + D[h]*v; RMS-norm; out = gate * silu(onw * xn).
// Output written as fp16 (feeds the final fp16 GEMM).
// ---------------------------------------------------------------------------
__global__ __launch_bounds__(128) void epilogue(const float* __restrict__ o_scan,
                                                const float* __restrict__ v,
                                                const float* __restrict__ gate,
                                                const float* __restrict__ D,
                                                const float* __restrict__ onw,
                                                __half* __restrict__ out) {
    int gw = blockIdx.x * 4 + (threadIdx.x >> 5);
    int lane = threadIdx.x & 31;
    int t = gw >> 5, h = gw & 31;
    size_t base = (size_t)t * KD + h * DH;
    float d = D[h];
    float o0 = o_scan[base + lane]      + d * v[base + lane];
    float o1 = o_scan[base + lane + 32] + d * v[base + lane + 32];
    float ss = o0 * o0 + o1 * o1;
#pragma unroll
    for (int off = 16; off; off >>= 1) ss += __shfl_xor_sync(0xffffffffu, ss, off);
    float r = rsqrtf(ss * (1.f / 64.f) + 1e-6f);
    float z0 = onw[lane]      * o0 * r;
    float z1 = onw[lane + 32] * o1 * r;
    out[base + lane]      = __float2half_rn(gate[base + lane]      * z0 / (1.f + expf(-z0)));
    out[base + lane + 32] = __float2half_rn(gate[base + lane + 32] * z1 / (1.f + expf(-z1)));
}

// ---------------------------------------------------------------------------
extern "C" void kernel_launch(void* const* d_in, const int* in_sizes, int n_in,
                              void* d_out, int out_size) {
    const float* x       = (const float*)d_in[0];
    const float* Wq      = (const float*)d_in[1];
    const float* Wk      = (const float*)d_in[2];
    const float* Wv      = (const float*)d_in[3];
    const float* Wg      = (const float*)d_in[4];
    const float* Wo      = (const float*)d_in[5];
    const float* Wb      = (const float*)d_in[6];
    const float* bb      = (const float*)d_in[7];
    const float* Wgk     = (const float*)d_in[8];
    const float* bgk     = (const float*)d_in[9];
    const float* wq_conv = (const float*)d_in[10];
    const float* bq_conv = (const float*)d_in[11];
    const float* wk_conv = (const float*)d_in[12];
    const float* bk_conv = (const float*)d_in[13];
    const float* wv_conv = (const float*)d_in[14];
    const float* bv_conv = (const float*)d_in[15];
    const float* A_log   = (const float*)d_in[16];
    const float* Dp      = (const float*)d_in[17];
    const float* dt_bias = (const float*)d_in[18];
    const float* onorm_w = (const float*)d_in[19];
    float* out = (float*)d_out;

    float* S;
    cudaGetSymbolAddress((void**)&S, g_scratch);
    __half* Hb;
    cudaGetSymbolAddress((void**)&Hb, g_half);

    float* bq  = S + OFF_Q;
    float* bk  = S + OFF_K;
    float* bv  = S + OFF_V;
    float* bqc = S + OFF_QC;
    float* bkc = S + OFF_KC;
    float* bvc = S + OFF_VC;
    float* bg  = S + OFF_G;
    float* bo  = S + OFF_O;
    float* bal = S + OFF_AL;
    float* bbe = S + OFF_BE;

    __half* xh  = Hb + HOFF_X;
    __half* wqh = Hb + HOFF_WQ;
    __half* wkh = Hb + HOFF_WK;
    __half* wvh = Hb + HOFF_WV;
    __half* wgh = Hb + HOFF_WG;
    __half* woh = Hb + HOFF_WO;
    __half* oh  = Hb + HOFF_O;

    static int attr_set = 0;
    if (!attr_set) {
        cudaFuncSetAttribute(gemm_f16<true>, cudaFuncAttributeMaxDynamicSharedMemorySize,
                             GEMM_SMEM);
        cudaFuncSetAttribute(gemm_f16<false>, cudaFuncAttributeMaxDynamicSharedMemorySize,
                             GEMM_SMEM);
        attr_set = 1;
    }

    dim3 gth(NE / 4 / 256, 6);
    to_half<<<gth, 256>>>(x, xh, Wq, wqh, Wk, wkh, Wv, wvh, Wg, wgh, Wo, woh);

    // Fused q/k/v/g projection: B = concat(Wq,Wk,Wv,Wg) (contiguous in g_half),
    // outputs to contiguous bq..bg regions via SPLIT mapping.
    dim3 gproj(64, 16);
    gemm_f16<true><<<gproj, 256, GEMM_SMEM>>>(xh, wqh, bq);

    bproj<<<64, 256>>>(x, Wb, bb, Wgk, bgk, A_log, dt_bias, bal, bbe);

    dim3 gcv(TT * KD / 256, 3);
    conv_silu<<<gcv, 256>>>(bq, wq_conv, bq_conv, bqc,
                            bk, wk_conv, bk_conv, bkc,
                            bv, wv_conv, bv_conv, bvc);

    dim3 gr(TT * NH / 4, 2);
    rope_l2norm<<<gr, 128>>>(bqc, bkc);

    scan_kernel<<<NH * 2, 128>>>(bqc, bkc, bvc, bal, bbe, bo);

    epilogue<<<TT * NH / 4, 128>>>(bo, bvc, bg, Dp, onorm_w, oh);

    dim3 g16(16, 16);
    gemm_f16<false><<<g16, 256, GEMM_SMEM>>>(oh, woh, out);
}

// round 13
// speedup vs baseline: 1.0772x; 1.0772x over previous
#include <cuda_runtime.h>
#include <cuda_fp16.h>
#include <math.h>
#include <stdint.h>

#define TT 2048
#define HIDD 2048
#define NH 32
#define DH 64
#define KD 2048
#define NE (2048u*2048u)

// fp32 scratch: q,k,v,g, qc,kc,vc, o_scan + alpha/beta
__device__ __align__(16) float g_scratch[8ull*NE + 2ull*TT*NH];
// fp16 scratch: xh, wqh, wkh, wvh, wgh, woh, oh   (wqh..wgh contiguous!)
__device__ __align__(16) __half g_half[7ull*NE];

#define OFF_Q  (0ull*NE)
#define OFF_K  (1ull*NE)
#define OFF_V  (2ull*NE)
#define OFF_G  (3ull*NE)
#define OFF_QC (4ull*NE)
#define OFF_KC (5ull*NE)
#define OFF_VC (6ull*NE)
#define OFF_O  (7ull*NE)
#define OFF_AL (8ull*NE)
#define OFF_BE (8ull*NE + (unsigned long long)TT*NH)

#define HOFF_X  (0ull*NE)
#define HOFF_WQ (1ull*NE)
#define HOFF_WK (2ull*NE)
#define HOFF_WV (3ull*NE)
#define HOFF_WG (4ull*NE)
#define HOFF_WO (5ull*NE)
#define HOFF_O  (6ull*NE)

typedef unsigned long long u64;

// ---------------------------------------------------------------------------
// FP16 tensor-core NT GEMM: C[m,n] = sum_k A[m*K+k]*B[n*K+k], fp32 accum.
// Block 128x128, BK=32 halves, 8 warps (4m x 2n) of 32x64, mma.m16n8k16.
// SPLIT=true: bx spans 4 concatenated weight/output regions (projection fuse).
// ---------------------------------------------------------------------------
#define GK 2048
#define HTILE_BYTES (128*80)          // 10240 per matrix
#define HSTG (2*HTILE_BYTES)          // 20480 per stage (A+B)
#define GEMM_SMEM (2u*HSTG)           // 40960, double buffered

__device__ __forceinline__ void cp_async16(uint32_t saddr, const void* gptr) {
    asm volatile("cp.async.ca.shared.global [%0], [%1], 16;\n" :: "r"(saddr), "l"(gptr));
}

__device__ __forceinline__ void ldsm4(uint32_t* r, uint32_t addr) {
    asm volatile("ldmatrix.sync.aligned.m8n8.x4.shared.b16 {%0,%1,%2,%3}, [%4];"
                 : "=r"(r[0]), "=r"(r[1]), "=r"(r[2]), "=r"(r[3]) : "r"(addr));
}

__device__ __forceinline__ void mma16(float* c, const uint32_t* a, const uint32_t* b) {
    asm volatile(
        "mma.sync.aligned.m16n8k16.row.col.f32.f16.f16.f32 "
        "{%0,%1,%2,%3},{%4,%5,%6,%7},{%8,%9},{%0,%1,%2,%3};\n"
        : "+f"(c[0]), "+f"(c[1]), "+f"(c[2]), "+f"(c[3])
        : "r"(a[0]), "r"(a[1]), "r"(a[2]), "r"(a[3]), "r"(b[0]), "r"(b[1]));
}

template<bool SPLIT>
__global__ __launch_bounds__(256, 2) void gemm_f16(const __half* __restrict__ A,
                                                   const __half* __restrict__ B,
                                                   float* __restrict__ C) {
    extern __shared__ char dsm[];
    const int tid = threadIdx.x;
    const int warp = tid >> 5, lane = tid & 31;
    const int grp = lane >> 2, tig = lane & 3;
    const int wm = (warp >> 1) * 32, wn = (warp & 1) * 64;
    const int bx = blockIdx.x, by = blockIdx.y;

    const __half* Ag = A + (size_t)(by * 128) * GK;
    const __half* Bg = B + (size_t)(bx * 128) * GK;   // weights contiguous across regions

    float* Cb;
    int gnb;
    if (SPLIT) {
        Cb = C + (size_t)(bx >> 4) * NE;
        gnb = (bx & 15) * 128;
    } else {
        Cb = C;
        gnb = bx * 128;
    }

    float c[2][8][4];
#pragma unroll
    for (int mi = 0; mi < 2; mi++)
#pragma unroll
        for (int nj = 0; nj < 8; nj++)
#pragma unroll
            for (int r = 0; r < 4; r++) c[mi][nj][r] = 0.f;

    const uint32_t smbase = (uint32_t)__cvta_generic_to_shared(dsm);
    const int NKI = GK / 32;

    const int a_r  = (lane & 7) + ((lane >> 3) & 1) * 8;
    const int a_c8 = ((lane >> 4) & 1) * 8;
    const int b_r  = (lane & 7) + ((lane >> 4) & 1) * 8;
    const int b_c8 = ((lane >> 3) & 1) * 8;

    // 128 rows * 4 chunks(16B) = 512 chunks per matrix; 256 threads -> 2 iters
    auto issue = [&](int s, int kt) {
        uint32_t stA = smbase + (uint32_t)(s * HSTG);
        uint32_t stB = stA + HTILE_BYTES;
#pragma unroll
        for (int i = 0; i < 2; i++) {
            int idx = tid + i * 256;      // 0..511
            int r = idx >> 2, ch = idx & 3;
            cp_async16(stA + (uint32_t)(r * 80 + ch * 16),
                       Ag + (size_t)r * GK + kt * 32 + ch * 8);
            cp_async16(stB + (uint32_t)(r * 80 + ch * 16),
                       Bg + (size_t)r * GK + kt * 32 + ch * 8);
        }
        asm volatile("cp.async.commit_group;\n");
    };

    issue(0, 0);

    for (int kt = 0; kt < NKI; kt++) {
        const int s = kt & 1;
        if (kt + 1 < NKI) {
            issue((kt + 1) & 1, kt + 1);
            asm volatile("cp.async.wait_group 1;\n");
        } else {
            asm volatile("cp.async.wait_group 0;\n");
        }
        __syncthreads();

        uint32_t stA = smbase + (uint32_t)(s * HSTG);
        uint32_t stB = stA + HTILE_BYTES;

#pragma unroll
        for (int ks = 0; ks < 2; ks++) {
            uint32_t av[2][4], bv[8][2];
#pragma unroll
            for (int mi = 0; mi < 2; mi++) {
                uint32_t addr = stA + (uint32_t)((wm + mi * 16 + a_r) * 80
                                                 + (ks * 16 + a_c8) * 2);
                ldsm4(av[mi], addr);
            }
#pragma unroll
            for (int njp = 0; njp < 4; njp++) {
                uint32_t r4[4];
                uint32_t addr = stB + (uint32_t)((wn + njp * 16 + b_r) * 80
                                                 + (ks * 16 + b_c8) * 2);
                ldsm4(r4, addr);
                bv[njp * 2][0] = r4[0]; bv[njp * 2][1] = r4[1];
                bv[njp * 2 + 1][0] = r4[2]; bv[njp * 2 + 1][1] = r4[3];
            }
#pragma unroll
            for (int mi = 0; mi < 2; mi++)
#pragma unroll
                for (int nj = 0; nj < 8; nj++)
                    mma16(c[mi][nj], av[mi], bv[nj]);
        }
        __syncthreads();
    }

#pragma unroll
    for (int mi = 0; mi < 2; mi++) {
        const int gm = by * 128 + wm + mi * 16 + grp;
#pragma unroll
        for (int nj = 0; nj < 8; nj++) {
            const int gn = gnb + wn + nj * 8 + 2 * tig;
            *(float2*)(Cb + (size_t)gm * 2048 + gn) = make_float2(c[mi][nj][0], c[mi][nj][1]);
            *(float2*)(Cb + (size_t)(gm + 8) * 2048 + gn) = make_float2(c[mi][nj][2], c[mi][nj][3]);
        }
    }
}

// ---------------------------------------------------------------------------
// fp32 -> fp16 conversion of x + 5 weight matrices.
// ---------------------------------------------------------------------------
__global__ __launch_bounds__(256) void to_half(const float* __restrict__ s0, __half* __restrict__ d0,
                                               const float* __restrict__ s1, __half* __restrict__ d1,
                                               const float* __restrict__ s2, __half* __restrict__ d2,
                                               const float* __restrict__ s3, __half* __restrict__ d3,
                                               const float* __restrict__ s4, __half* __restrict__ d4,
                                               const float* __restrict__ s5, __half* __restrict__ d5) {
    const float* s; __half* d;
    switch (blockIdx.y) {
        case 0: s = s0; d = d0; break;
        case 1: s = s1; d = d1; break;
        case 2: s = s2; d = d2; break;
        case 3: s = s3; d = d3; break;
        case 4: s = s4; d = d4; break;
        default: s = s5; d = d5; break;
    }
    unsigned i = blockIdx.x * 256u + threadIdx.x;
    float4 v = ((const float4*)s)[i];
    __half2 lo = __floats2half2_rn(v.x, v.y);
    __half2 hi = __floats2half2_rn(v.z, v.w);
    ((__half2*)d)[2 * i] = lo;
    ((__half2*)d)[2 * i + 1] = hi;
}

// ---------------------------------------------------------------------------
// Causal depthwise conv (K=4) + SiLU. blockIdx.y selects q/k/v.
// ---------------------------------------------------------------------------
__global__ __launch_bounds__(256) void conv_silu(const float* __restrict__ in0,
                                                 const float* __restrict__ w0,
                                                 const float* __restrict__ b0,
                                                 float* __restrict__ out0,
                                                 const float* __restrict__ in1,
                                                 const float* __restrict__ w1,
                                                 const float* __restrict__ b1,
                                                 float* __restrict__ out1,
                                                 const float* __restrict__ in2,
                                                 const float* __restrict__ w2,
                                                 const float* __restrict__ b2,
                                                 float* __restrict__ out2) {
    const float *in, *w, *b; float* out;
    switch (blockIdx.y) {
        case 0: in = in0; w = w0; b = b0; out = out0; break;
        case 1: in = in1; w = w1; b = b1; out = out1; break;
        default: in = in2; w = w2; b = b2; out = out2; break;
    }
    unsigned idx = blockIdx.x * 256u + threadIdx.x;
    int c = idx & (KD - 1);
    int t = idx >> 11;
    float4 w4 = ((const float4*)w)[c];
    float y = b[c];
    int ts = t - 3;
    if (ts >= 0)     y += in[(size_t)ts * KD + c] * w4.x;
    if (ts + 1 >= 0) y += in[(size_t)(ts + 1) * KD + c] * w4.y;
    if (ts + 2 >= 0) y += in[(size_t)(ts + 2) * KD + c] * w4.z;
    y += in[(size_t)t * KD + c] * w4.w;
    out[idx] = y / (1.f + expf(-y));
}

// ---------------------------------------------------------------------------
// beta/alpha via tiled fp32 mini-GEMM (exact fp32; feeds the scan).
// ---------------------------------------------------------------------------
__global__ __launch_bounds__(256) void bproj(const float* __restrict__ x,
                                             const float* __restrict__ Wb,
                                             const float* __restrict__ bb,
                                             const float* __restrict__ Wgk,
                                             const float* __restrict__ bgk,
                                             const float* __restrict__ A_log,
                                             const float* __restrict__ dt_bias,
                                             float* __restrict__ alpha,
                                             float* __restrict__ beta) {
    __shared__ __align__(16) float xs[32][33];
    __shared__ __align__(16) float ws[64][33];
    const int tid = threadIdx.x;
    const int t0 = blockIdx.x * 32;
    const int tn = tid & 15, tt = tid >> 4;
    const int tr = (tt & 15) * 2;
    const int nc = tn * 4;

    float acc[2][4];
#pragma unroll
    for (int i = 0; i < 2; i++)
#pragma unroll
        for (int j = 0; j < 4; j++) acc[i][j] = 0.f;

    for (int k0 = 0; k0 < HIDD; k0 += 32) {
        {
            int row = tid >> 3, kc = (tid & 7) * 4;
            float4 v4 = *(const float4*)&x[(size_t)(t0 + row) * HIDD + k0 + kc];
            xs[row][kc] = v4.x; xs[row][kc + 1] = v4.y;
            xs[row][kc + 2] = v4.z; xs[row][kc + 3] = v4.w;
        }
#pragma unroll
        for (int r = 0; r < 2; r++) {
            int idx = tid + r * 256;
            int n = idx >> 3, kc = (idx & 7) * 4;
            const float* src = (n < 32) ? &Wb[(size_t)n * HIDD + k0 + kc]
                                        : &Wgk[(size_t)(n - 32) * HIDD + k0 + kc];
            float4 v4 = *(const float4*)src;
            ws[n][kc] = v4.x; ws[n][kc + 1] = v4.y;
            ws[n][kc + 2] = v4.z; ws[n][kc + 3] = v4.w;
        }
        __syncthreads();
#pragma unroll
        for (int kk = 0; kk < 32; kk++) {
            float xa0 = xs[tr][kk], xa1 = xs[tr + 1][kk];
            float w0 = ws[nc][kk], w1 = ws[nc + 1][kk];
            float w2 = ws[nc + 2][kk], w3 = ws[nc + 3][kk];
            acc[0][0] += xa0 * w0; acc[0][1] += xa0 * w1;
            acc[0][2] += xa0 * w2; acc[0][3] += xa0 * w3;
            acc[1][0] += xa1 * w0; acc[1][1] += xa1 * w1;
            acc[1][2] += xa1 * w2; acc[1][3] += xa1 * w3;
        }
        __syncthreads();
    }

#pragma unroll
    for (int i = 0; i < 2; i++) {
        int t = t0 + tr + i;
#pragma unroll
        for (int j = 0; j < 4; j++) {
            int n = nc + j;
            if (n < 32) {
                beta[t * NH + n] = 1.f / (1.f + expf(-(acc[i][j] + bb[n])));
            } else {
                int h = n - 32;
                float z = acc[i][j] + bgk[h] + dt_bias[h];
                float sp = fmaxf(z, 0.f) + log1pf(expf(-fabsf(z)));
                alpha[t * NH + h] = expf(-expf(A_log[h]) * sp);
            }
        }
    }
}

// ---------------------------------------------------------------------------
// YaRN RoPE + l2norm, in-place.
// ---------------------------------------------------------------------------
__global__ __launch_bounds__(128) void rope_l2norm(float* __restrict__ q,
                                                   float* __restrict__ k) {
    int gw = blockIdx.x * 4 + (threadIdx.x >> 5);
    int lane = threadIdx.x & 31;
    int t = gw >> 5;
    int h = gw & 31;
    float* base = (blockIdx.y == 0 ? q : k) + (size_t)t * KD + h * DH;

    int m = (2 * lane) & 31;
    double invf = pow(10000.0, -((double)(2 * m) / 64.0));
    double wl = 6.283185307179586 / invf;
    double ramp = (wl - 1.0) / 31.0;
    ramp = ramp < 0.0 ? 0.0 : (ramp > 1.0 ? 1.0 : ramp);
    double scale = 1.0 + 31.0 * ramp;
    float f = (float)(((double)t / scale) * invf);
    float s, c;
    sincosf(f, &s, &c);

    float x1 = base[2 * lane];
    float x2 = base[2 * lane + 1];
    __syncwarp();
    float lo = x1 * c - x2 * s;
    float hi = x1 * s + x2 * c;
    float ss = lo * lo + hi * hi;
#pragma unroll
    for (int off = 16; off; off >>= 1) ss += __shfl_xor_sync(0xffffffffu, ss, off);
    float r = rsqrtf(ss + 1e-6f);
    base[lane] = lo * r;
    base[lane + 32] = hi * r;
}

// ---------------------------------------------------------------------------
// Sequential delta-rule scan (packed f32x2). One block per head; 128 threads.
// (R11 configuration — known good: 1 shfl on the serial chain.)
// ---------------------------------------------------------------------------
__device__ __forceinline__ u64 pk2(float lo, float hi) {
    u64 r; asm("mov.b64 %0,{%1,%2};" : "=l"(r) : "f"(lo), "f"(hi)); return r;
}
__device__ __forceinline__ void up2(u64 v, float& lo, float& hi) {
    asm("mov.b64 {%0,%1},%2;" : "=f"(lo), "=f"(hi) : "l"(v));
}
__device__ __forceinline__ u64 fma2(u64 a, u64 b, u64 c) {
    u64 d; asm("fma.rn.f32x2 %0,%1,%2,%3;" : "=l"(d) : "l"(a), "l"(b), "l"(c)); return d;
}
__device__ __forceinline__ u64 mul2(u64 a, u64 b) {
    u64 d; asm("mul.rn.f32x2 %0,%1,%2;" : "=l"(d) : "l"(a), "l"(b)); return d;
}

#define CH 32
__global__ __launch_bounds__(128) void scan_kernel(const float* __restrict__ q,
                                                   const float* __restrict__ k,
                                                   const float* __restrict__ v,
                                                   const float* __restrict__ alpha,
                                                   const float* __restrict__ beta,
                                                   float* __restrict__ o) {
    int h = blockIdx.x;
    __shared__ __align__(16) float sq[CH][DH];
    __shared__ __align__(16) float sk[CH][DH];
    __shared__ __align__(16) float sv[CH][DH];
    __shared__ __align__(16) float so[CH][DH];
    __shared__ float sa[CH], sb2[CH];

    int tid = threadIdx.x;
    int j = tid >> 1;
    int hf = tid & 1;
    int base = hf * 32;

    u64 S2[16];
#pragma unroll
    for (int i = 0; i < 16; i++) S2[i] = 0ull;

    for (int t0 = 0; t0 < TT; t0 += CH) {
#pragma unroll
        for (int r = 0; r < 4; r++) {
            int fi = tid + r * 128;
            int s = fi >> 4;
            int d4 = fi & 15;
            size_t gidx = (size_t)(t0 + s) * KD + h * DH + d4 * 4;
            ((float4*)sq[s])[d4] = *(const float4*)&q[gidx];
            ((float4*)sk[s])[d4] = *(const float4*)&k[gidx];
            ((float4*)sv[s])[d4] = *(const float4*)&v[gidx];
        }
        if (tid < CH) {
            sa[tid]  = alpha[(t0 + tid) * NH + h];
            sb2[tid] = beta[(t0 + tid) * NH + h];
        }
        __syncthreads();

        for (int s = 0; s < CH; s++) {
            const u64* k2 = (const u64*)&sk[s][base];
            const u64* q2 = (const u64*)&sq[s][base];
            u64 e0 = 0ull, e1 = 0ull, e2 = 0ull, e3 = 0ull;
#pragma unroll
            for (int ii = 0; ii < 16; ii += 4) {
                e0 = fma2(k2[ii],     S2[ii],     e0);
                e1 = fma2(k2[ii + 1], S2[ii + 1], e1);
                e2 = fma2(k2[ii + 2], S2[ii + 2], e2);
                e3 = fma2(k2[ii + 3], S2[ii + 3], e3);
            }
            float l0, h0, l1, h1, l2, h2, l3, h3;
            up2(e0, l0, h0); up2(e1, l1, h1); up2(e2, l2, h2); up2(e3, l3, h3);
            float errdot = ((l0 + h0) + (l1 + h1)) + ((l2 + h2) + (l3 + h3));
            errdot += __shfl_xor_sync(0xffffffffu, errdot, 1);
            float a = sa[s];
            float u = sb2[s] * (sv[s][j] - a * errdot);
            u64 ab = pk2(a, a), ub = pk2(u, u);
            u64 o0 = 0ull, o1 = 0ull, o2 = 0ull, o3 = 0ull;
#pragma unroll
            for (int ii = 0; ii < 16; ii += 4) {
                S2[ii]     = fma2(k2[ii],     ub, mul2(ab, S2[ii]));
                S2[ii + 1] = fma2(k2[ii + 1], ub, mul2(ab, S2[ii + 1]));
                S2[ii + 2] = fma2(k2[ii + 2], ub, mul2(ab, S2[ii + 2]));
                S2[ii + 3] = fma2(k2[ii + 3], ub, mul2(ab, S2[ii + 3]));
                o0 = fma2(q2[ii],     S2[ii],     o0);
                o1 = fma2(q2[ii + 1], S2[ii + 1], o1);
                o2 = fma2(q2[ii + 2], S2[ii + 2], o2);
                o3 = fma2(q2[ii + 3], S2[ii + 3], o3);
            }
            up2(o0, l0, h0); up2(o1, l1, h1); up2(o2, l2, h2); up2(o3, l3, h3);
            float ov = ((l0 + h0) + (l1 + h1)) + ((l2 + h2) + (l3 + h3));
            ov += __shfl_xor_sync(0xffffffffu, ov, 1);
            if (hf == 0) so[s][j] = ov;
        }
        __syncthreads();
#pragma unroll
        for (int r = 0; r < 4; r++) {
            int fi = tid + r * 128;
            int s = fi >> 4;
            int d4 = fi & 15;
            *(float4*)&o[(size_t)(t0 + s) * KD + h * DH + d4 * 4] = ((float4*)so[s])[d4];
        }
    }
}

// ---------------------------------------------------------------------------
// Epilogue: o = o_scan + D[h]*v; RMS-norm; out = gate * silu(onw * xn).
// Output written as fp16 (feeds the final fp16 GEMM).
// ---------------------------------------------------------------------------
__global__ __launch_bounds__(128) void epilogue(const float* __restrict__ o_scan,
                                                const float* __restrict__ v,
                                                const float* __restrict__ gate,
                                                const float* __restrict__ D,
                                                const float* __restrict__ onw,
                                                __half* __restrict__ out) {
    int gw = blockIdx.x * 4 + (threadIdx.x >> 5);
    int lane = threadIdx.x & 31;
    int t = gw >> 5, h = gw & 31;
    size_t base = (size_t)t * KD + h * DH;
    float d = D[h];
    float o0 = o_scan[base + lane]      + d * v[base + lane];
    float o1 = o_scan[base + lane + 32] + d * v[base + lane + 32];
    float ss = o0 * o0 + o1 * o1;
#pragma unroll
    for (int off = 16; off; off >>= 1) ss += __shfl_xor_sync(0xffffffffu, ss, off);
    float r = rsqrtf(ss * (1.f / 64.f) + 1e-6f);
    float z0 = onw[lane]      * o0 * r;
    float z1 = onw[lane + 32] * o1 * r;
    out[base + lane]      = __float2half_rn(gate[base + lane]      * z0 / (1.f + expf(-z0)));
    out[base + lane + 32] = __float2half_rn(gate[base + lane + 32] * z1 / (1.f + expf(-z1)));
}

// ---------------------------------------------------------------------------
extern "C" void kernel_launch(void* const* d_in, const int* in_sizes, int n_in,
                              void* d_out, int out_size) {
    const float* x       = (const float*)d_in[0];
    const float* Wq      = (const float*)d_in[1];
    const float* Wk      = (const float*)d_in[2];
    const float* Wv      = (const float*)d_in[3];
    const float* Wg      = (const float*)d_in[4];
    const float* Wo      = (const float*)d_in[5];
    const float* Wb      = (const float*)d_in[6];
    const float* bb      = (const float*)d_in[7];
    const float* Wgk     = (const float*)d_in[8];
    const float* bgk     = (const float*)d_in[9];
    const float* wq_conv = (const float*)d_in[10];
    const float* bq_conv = (const float*)d_in[11];
    const float* wk_conv = (const float*)d_in[12];
    const float* bk_conv = (const float*)d_in[13];
    const float* wv_conv = (const float*)d_in[14];
    const float* bv_conv = (const float*)d_in[15];
    const float* A_log   = (const float*)d_in[16];
    const float* Dp      = (const float*)d_in[17];
    const float* dt_bias = (const float*)d_in[18];
    const float* onorm_w = (const float*)d_in[19];
    float* out = (float*)d_out;

    float* S;
    cudaGetSymbolAddress((void**)&S, g_scratch);
    __half* Hb;
    cudaGetSymbolAddress((void**)&Hb, g_half);

    float* bq  = S + OFF_Q;
    float* bk  = S + OFF_K;
    float* bv  = S + OFF_V;
    float* bg  = S + OFF_G;
    float* bqc = S + OFF_QC;
    float* bkc = S + OFF_KC;
    float* bvc = S + OFF_VC;
    float* bo  = S + OFF_O;
    float* bal = S + OFF_AL;
    float* bbe = S + OFF_BE;

    __half* xh  = Hb + HOFF_X;
    __half* wqh = Hb + HOFF_WQ;
    __half* wkh = Hb + HOFF_WK;
    __half* wvh = Hb + HOFF_WV;
    __half* wgh = Hb + HOFF_WG;
    __half* woh = Hb + HOFF_WO;
    __half* oh  = Hb + HOFF_O;

    static int attr_set = 0;
    if (!attr_set) {
        cudaFuncSetAttribute(gemm_f16<true>, cudaFuncAttributeMaxDynamicSharedMemorySize,
                             GEMM_SMEM);
        cudaFuncSetAttribute(gemm_f16<false>, cudaFuncAttributeMaxDynamicSharedMemorySize,
                             GEMM_SMEM);
        attr_set = 1;
    }

    dim3 gth(NE / 4 / 256, 6);
    to_half<<<gth, 256>>>(x, xh, Wq, wqh, Wk, wkh, Wv, wvh, Wg, wgh, Wo, woh);

    // Fused q/k/v/g projection: B = concat(Wq,Wk,Wv,Wg) (contiguous in g_half),
    // outputs to contiguous bq..bg regions via SPLIT mapping.
    dim3 gproj(64, 16);
    gemm_f16<true><<<gproj, 256, GEMM_SMEM>>>(xh, wqh, bq);

    bproj<<<64, 256>>>(x, Wb, bb, Wgk, bgk, A_log, dt_bias, bal, bbe);

    dim3 gcv(TT * KD / 256, 3);
    conv_silu<<<gcv, 256>>>(bq, wq_conv, bq_conv, bqc,
                            bk, wk_conv, bk_conv, bkc,
                            bv, wv_conv, bv_conv, bvc);

    dim3 gr(TT * NH / 4, 2);
    rope_l2norm<<<gr, 128>>>(bqc, bkc);

    scan_kernel<<<NH, 128>>>(bqc, bkc, bvc, bal, bbe, bo);

    epilogue<<<TT * NH / 4, 128>>>(bo, bvc, bg, Dp, onorm_w, oh);

    dim3 g16(16, 16);
    gemm_f16<false><<<g16, 256, GEMM_SMEM>>>(oh, woh, out);
}

// round 14
// speedup vs baseline: 1.1282x; 1.0473x over previous
#include <cuda_runtime.h>
#include <cuda_fp16.h>
#include <math.h>
#include <stdint.h>

#define TT 2048
#define HIDD 2048
#define NH 32
#define DH 64
#define KD 2048
#define NE (2048u*2048u)

// fp32 scratch: q,k,v,g, qc,kc,vc, o_scan + alpha/beta
__device__ __align__(16) float g_scratch[8ull*NE + 2ull*TT*NH];
// fp16 scratch: xh, wqh, wkh, wvh, wgh, woh, oh   (wqh..wgh contiguous!)
__device__ __align__(16) __half g_half[7ull*NE];

#define OFF_Q  (0ull*NE)
#define OFF_K  (1ull*NE)
#define OFF_V  (2ull*NE)
#define OFF_G  (3ull*NE)
#define OFF_QC (4ull*NE)
#define OFF_KC (5ull*NE)
#define OFF_VC (6ull*NE)
#define OFF_O  (7ull*NE)
#define OFF_AL (8ull*NE)
#define OFF_BE (8ull*NE + (unsigned long long)TT*NH)

#define HOFF_X  (0ull*NE)
#define HOFF_WQ (1ull*NE)
#define HOFF_WK (2ull*NE)
#define HOFF_WV (3ull*NE)
#define HOFF_WG (4ull*NE)
#define HOFF_WO (5ull*NE)
#define HOFF_O  (6ull*NE)

typedef unsigned long long u64;

// ---------------------------------------------------------------------------
// FP16 tensor-core NT GEMM: C[m,n] = sum_k A[m*K+k]*B[n*K+k], fp32 accum.
// Block 128x128, BK=32 halves, 8 warps (4m x 2n) of 32x64, mma.m16n8k16.
// 3-stage cp.async pipeline.  SPLIT=true: bx spans 4 concatenated regions.
// ---------------------------------------------------------------------------
#define GK 2048
#define HTILE_BYTES (128*80)          // 10240 per matrix
#define HSTG (2*HTILE_BYTES)          // 20480 per stage (A+B)
#define NSTAGE 3
#define GEMM_SMEM (3u*HSTG)           // 61440

__device__ __forceinline__ void cp_async16(uint32_t saddr, const void* gptr) {
    asm volatile("cp.async.ca.shared.global [%0], [%1], 16;\n" :: "r"(saddr), "l"(gptr));
}

__device__ __forceinline__ void ldsm4(uint32_t* r, uint32_t addr) {
    asm volatile("ldmatrix.sync.aligned.m8n8.x4.shared.b16 {%0,%1,%2,%3}, [%4];"
                 : "=r"(r[0]), "=r"(r[1]), "=r"(r[2]), "=r"(r[3]) : "r"(addr));
}

__device__ __forceinline__ void mma16(float* c, const uint32_t* a, const uint32_t* b) {
    asm volatile(
        "mma.sync.aligned.m16n8k16.row.col.f32.f16.f16.f32 "
        "{%0,%1,%2,%3},{%4,%5,%6,%7},{%8,%9},{%0,%1,%2,%3};\n"
        : "+f"(c[0]), "+f"(c[1]), "+f"(c[2]), "+f"(c[3])
        : "r"(a[0]), "r"(a[1]), "r"(a[2]), "r"(a[3]), "r"(b[0]), "r"(b[1]));
}

template<bool SPLIT>
__global__ __launch_bounds__(256, 2) void gemm_f16(const __half* __restrict__ A,
                                                   const __half* __restrict__ B,
                                                   float* __restrict__ C) {
    extern __shared__ char dsm[];
    const int tid = threadIdx.x;
    const int warp = tid >> 5, lane = tid & 31;
    const int grp = lane >> 2, tig = lane & 3;
    const int wm = (warp >> 1) * 32, wn = (warp & 1) * 64;
    const int bx = blockIdx.x, by = blockIdx.y;

    const __half* Ag = A + (size_t)(by * 128) * GK;
    const __half* Bg = B + (size_t)(bx * 128) * GK;   // weights contiguous across regions

    float* Cb;
    int gnb;
    if (SPLIT) {
        Cb = C + (size_t)(bx >> 4) * NE;
        gnb = (bx & 15) * 128;
    } else {
        Cb = C;
        gnb = bx * 128;
    }

    float c[2][8][4];
#pragma unroll
    for (int mi = 0; mi < 2; mi++)
#pragma unroll
        for (int nj = 0; nj < 8; nj++)
#pragma unroll
            for (int r = 0; r < 4; r++) c[mi][nj][r] = 0.f;

    const uint32_t smbase = (uint32_t)__cvta_generic_to_shared(dsm);
    const int NKI = GK / 32;

    const int a_r  = (lane & 7) + ((lane >> 3) & 1) * 8;
    const int a_c8 = ((lane >> 4) & 1) * 8;
    const int b_r  = (lane & 7) + ((lane >> 4) & 1) * 8;
    const int b_c8 = ((lane >> 3) & 1) * 8;

    // 128 rows * 4 chunks(16B) = 512 chunks per matrix; 256 threads -> 2 iters
    auto issue = [&](int s, int kt) {
        uint32_t stA = smbase + (uint32_t)(s * HSTG);
        uint32_t stB = stA + HTILE_BYTES;
#pragma unroll
        for (int i = 0; i < 2; i++) {
            int idx = tid + i * 256;      // 0..511
            int r = idx >> 2, ch = idx & 3;
            cp_async16(stA + (uint32_t)(r * 80 + ch * 16),
                       Ag + (size_t)r * GK + kt * 32 + ch * 8);
            cp_async16(stB + (uint32_t)(r * 80 + ch * 16),
                       Bg + (size_t)r * GK + kt * 32 + ch * 8);
        }
        asm volatile("cp.async.commit_group;\n");
    };

    issue(0, 0);
    issue(1, 1);

    for (int kt = 0; kt < NKI; kt++) {
        if (kt + 2 < NKI) {
            issue((kt + 2) % NSTAGE, kt + 2);
            asm volatile("cp.async.wait_group 2;\n");
        } else if (kt + 1 < NKI) {
            asm volatile("cp.async.wait_group 1;\n");
        } else {
            asm volatile("cp.async.wait_group 0;\n");
        }
        __syncthreads();

        const int s = kt % NSTAGE;
        uint32_t stA = smbase + (uint32_t)(s * HSTG);
        uint32_t stB = stA + HTILE_BYTES;

#pragma unroll
        for (int ks = 0; ks < 2; ks++) {
            uint32_t av[2][4], bv[8][2];
#pragma unroll
            for (int mi = 0; mi < 2; mi++) {
                uint32_t addr = stA + (uint32_t)((wm + mi * 16 + a_r) * 80
                                                 + (ks * 16 + a_c8) * 2);
                ldsm4(av[mi], addr);
            }
#pragma unroll
            for (int njp = 0; njp < 4; njp++) {
                uint32_t r4[4];
                uint32_t addr = stB + (uint32_t)((wn + njp * 16 + b_r) * 80
                                                 + (ks * 16 + b_c8) * 2);
                ldsm4(r4, addr);
                bv[njp * 2][0] = r4[0]; bv[njp * 2][1] = r4[1];
                bv[njp * 2 + 1][0] = r4[2]; bv[njp * 2 + 1][1] = r4[3];
            }
#pragma unroll
            for (int mi = 0; mi < 2; mi++)
#pragma unroll
                for (int nj = 0; nj < 8; nj++)
                    mma16(c[mi][nj], av[mi], bv[nj]);
        }
        __syncthreads();
    }

#pragma unroll
    for (int mi = 0; mi < 2; mi++) {
        const int gm = by * 128 + wm + mi * 16 + grp;
#pragma unroll
        for (int nj = 0; nj < 8; nj++) {
            const int gn = gnb + wn + nj * 8 + 2 * tig;
            *(float2*)(Cb + (size_t)gm * 2048 + gn) = make_float2(c[mi][nj][0], c[mi][nj][1]);
            *(float2*)(Cb + (size_t)(gm + 8) * 2048 + gn) = make_float2(c[mi][nj][2], c[mi][nj][3]);
        }
    }
}

// ---------------------------------------------------------------------------
// fp32 -> fp16 conversion of x + 5 weight matrices.
// ---------------------------------------------------------------------------
__global__ __launch_bounds__(256) void to_half(const float* __restrict__ s0, __half* __restrict__ d0,
                                               const float* __restrict__ s1, __half* __restrict__ d1,
                                               const float* __restrict__ s2, __half* __restrict__ d2,
                                               const float* __restrict__ s3, __half* __restrict__ d3,
                                               const float* __restrict__ s4, __half* __restrict__ d4,
                                               const float* __restrict__ s5, __half* __restrict__ d5) {
    const float* s; __half* d;
    switch (blockIdx.y) {
        case 0: s = s0; d = d0; break;
        case 1: s = s1; d = d1; break;
        case 2: s = s2; d = d2; break;
        case 3: s = s3; d = d3; break;
        case 4: s = s4; d = d4; break;
        default: s = s5; d = d5; break;
    }
    unsigned i = blockIdx.x * 256u + threadIdx.x;
    float4 v = ((const float4*)s)[i];
    __half2 lo = __floats2half2_rn(v.x, v.y);
    __half2 hi = __floats2half2_rn(v.z, v.w);
    ((__half2*)d)[2 * i] = lo;
    ((__half2*)d)[2 * i + 1] = hi;
}

// ---------------------------------------------------------------------------
// Causal depthwise conv (K=4) + SiLU, 4 timesteps per thread.
// blockIdx.y selects q/k/v.  7 loads + 4 stores per thread.
// ---------------------------------------------------------------------------
__global__ __launch_bounds__(256) void conv_silu(const float* __restrict__ in0,
                                                 const float* __restrict__ w0,
                                                 const float* __restrict__ b0,
                                                 float* __restrict__ out0,
                                                 const float* __restrict__ in1,
                                                 const float* __restrict__ w1,
                                                 const float* __restrict__ b1,
                                                 float* __restrict__ out1,
                                                 const float* __restrict__ in2,
                                                 const float* __restrict__ w2,
                                                 const float* __restrict__ b2,
                                                 float* __restrict__ out2) {
    const float *in, *w, *b; float* out;
    switch (blockIdx.y) {
        case 0: in = in0; w = w0; b = b0; out = out0; break;
        case 1: in = in1; w = w1; b = b1; out = out1; break;
        default: in = in2; w = w2; b = b2; out = out2; break;
    }
    unsigned idx = blockIdx.x * 256u + threadIdx.x;   // over (tgroup, c)
    int c = idx & (KD - 1);
    int t0 = (int)(idx >> 11) * 4;
    float4 w4 = ((const float4*)w)[c];
    float bias = b[c];

    const float* p = in + (size_t)t0 * KD + c;
    float xm3, xm2, xm1;
    if (t0 == 0) {
        xm3 = 0.f; xm2 = 0.f; xm1 = 0.f;
    } else {
        xm3 = p[-3 * (int)KD]; xm2 = p[-2 * (int)KD]; xm1 = p[-(int)KD];
    }
    float x0 = p[0];
    float x1 = p[KD];
    float x2 = p[2 * KD];
    float x3 = p[3 * KD];

    float y0 = bias + xm3 * w4.x + xm2 * w4.y + xm1 * w4.z + x0 * w4.w;
    float y1 = bias + xm2 * w4.x + xm1 * w4.y + x0  * w4.z + x1 * w4.w;
    float y2 = bias + xm1 * w4.x + x0  * w4.y + x1  * w4.z + x2 * w4.w;
    float y3 = bias + x0  * w4.x + x1  * w4.y + x2  * w4.z + x3 * w4.w;

    float* q = out + (size_t)t0 * KD + c;
    q[0]      = y0 / (1.f + expf(-y0));
    q[KD]     = y1 / (1.f + expf(-y1));
    q[2 * KD] = y2 / (1.f + expf(-y2));
    q[3 * KD] = y3 / (1.f + expf(-y3));
}

// ---------------------------------------------------------------------------
// beta/alpha via tiled fp32 mini-GEMM (exact fp32; feeds the scan).
// ---------------------------------------------------------------------------
__global__ __launch_bounds__(256) void bproj(const float* __restrict__ x,
                                             const float* __restrict__ Wb,
                                             const float* __restrict__ bb,
                                             const float* __restrict__ Wgk,
                                             const float* __restrict__ bgk,
                                             const float* __restrict__ A_log,
                                             const float* __restrict__ dt_bias,
                                             float* __restrict__ alpha,
                                             float* __restrict__ beta) {
    __shared__ __align__(16) float xs[32][33];
    __shared__ __align__(16) float ws[64][33];
    const int tid = threadIdx.x;
    const int t0 = blockIdx.x * 32;
    const int tn = tid & 15, tt = tid >> 4;
    const int tr = (tt & 15) * 2;
    const int nc = tn * 4;

    float acc[2][4];
#pragma unroll
    for (int i = 0; i < 2; i++)
#pragma unroll
        for (int j = 0; j < 4; j++) acc[i][j] = 0.f;

    for (int k0 = 0; k0 < HIDD; k0 += 32) {
        {
            int row = tid >> 3, kc = (tid & 7) * 4;
            float4 v4 = *(const float4*)&x[(size_t)(t0 + row) * HIDD + k0 + kc];
            xs[row][kc] = v4.x; xs[row][kc + 1] = v4.y;
            xs[row][kc + 2] = v4.z; xs[row][kc + 3] = v4.w;
        }
#pragma unroll
        for (int r = 0; r < 2; r++) {
            int idx = tid + r * 256;
            int n = idx >> 3, kc = (idx & 7) * 4;
            const float* src = (n < 32) ? &Wb[(size_t)n * HIDD + k0 + kc]
                                        : &Wgk[(size_t)(n - 32) * HIDD + k0 + kc];
            float4 v4 = *(const float4*)src;
            ws[n][kc] = v4.x; ws[n][kc + 1] = v4.y;
            ws[n][kc + 2] = v4.z; ws[n][kc + 3] = v4.w;
        }
        __syncthreads();
#pragma unroll
        for (int kk = 0; kk < 32; kk++) {
            float xa0 = xs[tr][kk], xa1 = xs[tr + 1][kk];
            float w0 = ws[nc][kk], w1 = ws[nc + 1][kk];
            float w2 = ws[nc + 2][kk], w3 = ws[nc + 3][kk];
            acc[0][0] += xa0 * w0; acc[0][1] += xa0 * w1;
            acc[0][2] += xa0 * w2; acc[0][3] += xa0 * w3;
            acc[1][0] += xa1 * w0; acc[1][1] += xa1 * w1;
            acc[1][2] += xa1 * w2; acc[1][3] += xa1 * w3;
        }
        __syncthreads();
    }

#pragma unroll
    for (int i = 0; i < 2; i++) {
        int t = t0 + tr + i;
#pragma unroll
        for (int j = 0; j < 4; j++) {
            int n = nc + j;
            if (n < 32) {
                beta[t * NH + n] = 1.f / (1.f + expf(-(acc[i][j] + bb[n])));
            } else {
                int h = n - 32;
                float z = acc[i][j] + bgk[h] + dt_bias[h];
                float sp = fmaxf(z, 0.f) + log1pf(expf(-fabsf(z)));
                alpha[t * NH + h] = expf(-expf(A_log[h]) * sp);
            }
        }
    }
}

// ---------------------------------------------------------------------------
// YaRN RoPE + l2norm, in-place.
// ---------------------------------------------------------------------------
__global__ __launch_bounds__(128) void rope_l2norm(float* __restrict__ q,
                                                   float* __restrict__ k) {
    int gw = blockIdx.x * 4 + (threadIdx.x >> 5);
    int lane = threadIdx.x & 31;
    int t = gw >> 5;
    int h = gw & 31;
    float* base = (blockIdx.y == 0 ? q : k) + (size_t)t * KD + h * DH;

    int m = (2 * lane) & 31;
    double invf = pow(10000.0, -((double)(2 * m) / 64.0));
    double wl = 6.283185307179586 / invf;
    double ramp = (wl - 1.0) / 31.0;
    ramp = ramp < 0.0 ? 0.0 : (ramp > 1.0 ? 1.0 : ramp);
    double scale = 1.0 + 31.0 * ramp;
    float f = (float)(((double)t / scale) * invf);
    float s, c;
    sincosf(f, &s, &c);

    float x1 = base[2 * lane];
    float x2 = base[2 * lane + 1];
    __syncwarp();
    float lo = x1 * c - x2 * s;
    float hi = x1 * s + x2 * c;
    float ss = lo * lo + hi * hi;
#pragma unroll
    for (int off = 16; off; off >>= 1) ss += __shfl_xor_sync(0xffffffffu, ss, off);
    float r = rsqrtf(ss + 1e-6f);
    base[lane] = lo * r;
    base[lane + 32] = hi * r;
}

// ---------------------------------------------------------------------------
// Sequential delta-rule scan (packed f32x2). One block per head; 128 threads.
// (R11/R13 configuration — known good: 1 shfl on the serial chain.)
// ---------------------------------------------------------------------------
__device__ __forceinline__ u64 pk2(float lo, float hi) {
    u64 r; asm("mov.b64 %0,{%1,%2};" : "=l"(r) : "f"(lo), "f"(hi)); return r;
}
__device__ __forceinline__ void up2(u64 v, float& lo, float& hi) {
    asm("mov.b64 {%0,%1},%2;" : "=f"(lo), "=f"(hi) : "l"(v));
}
__device__ __forceinline__ u64 fma2(u64 a, u64 b, u64 c) {
    u64 d; asm("fma.rn.f32x2 %0,%1,%2,%3;" : "=l"(d) : "l"(a), "l"(b), "l"(c)); return d;
}
__device__ __forceinline__ u64 mul2(u64 a, u64 b) {
    u64 d; asm("mul.rn.f32x2 %0,%1,%2;" : "=l"(d) : "l"(a), "l"(b)); return d;
}

#define CH 32
__global__ __launch_bounds__(128) void scan_kernel(const float* __restrict__ q,
                                                   const float* __restrict__ k,
                                                   const float* __restrict__ v,
                                                   const float* __restrict__ alpha,
                                                   const float* __restrict__ beta,
                                                   float* __restrict__ o) {
    int h = blockIdx.x;
    __shared__ __align__(16) float sq[CH][DH];
    __shared__ __align__(16) float sk[CH][DH];
    __shared__ __align__(16) float sv[CH][DH];
    __shared__ __align__(16) float so[CH][DH];
    __shared__ float sa[CH], sb2[CH];

    int tid = threadIdx.x;
    int j = tid >> 1;
    int hf = tid & 1;
    int base = hf * 32;

    u64 S2[16];
#pragma unroll
    for (int i = 0; i < 16; i++) S2[i] = 0ull;

    for (int t0 = 0; t0 < TT; t0 += CH) {
#pragma unroll
        for (int r = 0; r < 4; r++) {
            int fi = tid + r * 128;
            int s = fi >> 4;
            int d4 = fi & 15;
            size_t gidx = (size_t)(t0 + s) * KD + h * DH + d4 * 4;
            ((float4*)sq[s])[d4] = *(const float4*)&q[gidx];
            ((float4*)sk[s])[d4] = *(const float4*)&k[gidx];
            ((float4*)sv[s])[d4] = *(const float4*)&v[gidx];
        }
        if (tid < CH) {
            sa[tid]  = alpha[(t0 + tid) * NH + h];
            sb2[tid] = beta[(t0 + tid) * NH + h];
        }
        __syncthreads();

        for (int s = 0; s < CH; s++) {
            const u64* k2 = (const u64*)&sk[s][base];
            const u64* q2 = (const u64*)&sq[s][base];
            u64 e0 = 0ull, e1 = 0ull, e2 = 0ull, e3 = 0ull;
#pragma unroll
            for (int ii = 0; ii < 16; ii += 4) {
                e0 = fma2(k2[ii],     S2[ii],     e0);
                e1 = fma2(k2[ii + 1], S2[ii + 1], e1);
                e2 = fma2(k2[ii + 2], S2[ii + 2], e2);
                e3 = fma2(k2[ii + 3], S2[ii + 3], e3);
            }
            float l0, h0, l1, h1, l2, h2, l3, h3;
            up2(e0, l0, h0); up2(e1, l1, h1); up2(e2, l2, h2); up2(e3, l3, h3);
            float errdot = ((l0 + h0) + (l1 + h1)) + ((l2 + h2) + (l3 + h3));
            errdot += __shfl_xor_sync(0xffffffffu, errdot, 1);
            float a = sa[s];
            float u = sb2[s] * (sv[s][j] - a * errdot);
            u64 ab = pk2(a, a), ub = pk2(u, u);
            u64 o0 = 0ull, o1 = 0ull, o2 = 0ull, o3 = 0ull;
#pragma unroll
            for (int ii = 0; ii < 16; ii += 4) {
                S2[ii]     = fma2(k2[ii],     ub, mul2(ab, S2[ii]));
                S2[ii + 1] = fma2(k2[ii + 1], ub, mul2(ab, S2[ii + 1]));
                S2[ii + 2] = fma2(k2[ii + 2], ub, mul2(ab, S2[ii + 2]));
                S2[ii + 3] = fma2(k2[ii + 3], ub, mul2(ab, S2[ii + 3]));
                o0 = fma2(q2[ii],     S2[ii],     o0);
                o1 = fma2(q2[ii + 1], S2[ii + 1], o1);
                o2 = fma2(q2[ii + 2], S2[ii + 2], o2);
                o3 = fma2(q2[ii + 3], S2[ii + 3], o3);
            }
            up2(o0, l0, h0); up2(o1, l1, h1); up2(o2, l2, h2); up2(o3, l3, h3);
            float ov = ((l0 + h0) + (l1 + h1)) + ((l2 + h2) + (l3 + h3));
            ov += __shfl_xor_sync(0xffffffffu, ov, 1);
            if (hf == 0) so[s][j] = ov;
        }
        __syncthreads();
#pragma unroll
        for (int r = 0; r < 4; r++) {
            int fi = tid + r * 128;
            int s = fi >> 4;
            int d4 = fi & 15;
            *(float4*)&o[(size_t)(t0 + s) * KD + h * DH + d4 * 4] = ((float4*)so[s])[d4];
        }
    }
}

// ---------------------------------------------------------------------------
// Epilogue: o = o_scan + D[h]*v; RMS-norm; out = gate * silu(onw * xn).
// Output written as fp16 (feeds the final fp16 GEMM).
// ---------------------------------------------------------------------------
__global__ __launch_bounds__(128) void epilogue(const float* __restrict__ o_scan,
                                                const float* __restrict__ v,
                                                const float* __restrict__ gate,
                                                const float* __restrict__ D,
                                                const float* __restrict__ onw,
                                                __half* __restrict__ out) {
    int gw = blockIdx.x * 4 + (threadIdx.x >> 5);
    int lane = threadIdx.x & 31;
    int t = gw >> 5, h = gw & 31;
    size_t base = (size_t)t * KD + h * DH;
    float d = D[h];
    float o0 = o_scan[base + lane]      + d * v[base + lane];
    float o1 = o_scan[base + lane + 32] + d * v[base + lane + 32];
    float ss = o0 * o0 + o1 * o1;
#pragma unroll
    for (int off = 16; off; off >>= 1) ss += __shfl_xor_sync(0xffffffffu, ss, off);
    float r = rsqrtf(ss * (1.f / 64.f) + 1e-6f);
    float z0 = onw[lane]      * o0 * r;
    float z1 = onw[lane + 32] * o1 * r;
    out[base + lane]      = __float2half_rn(gate[base + lane]      * z0 / (1.f + expf(-z0)));
    out[base + lane + 32] = __float2half_rn(gate[base + lane + 32] * z1 / (1.f + expf(-z1)));
}

// ---------------------------------------------------------------------------
extern "C" void kernel_launch(void* const* d_in, const int* in_sizes, int n_in,
                              void* d_out, int out_size) {
    const float* x       = (const float*)d_in[0];
    const float* Wq      = (const float*)d_in[1];
    const float* Wk      = (const float*)d_in[2];
    const float* Wv      = (const float*)d_in[3];
    const float* Wg      = (const float*)d_in[4];
    const float* Wo      = (const float*)d_in[5];
    const float* Wb      = (const float*)d_in[6];
    const float* bb      = (const float*)d_in[7];
    const float* Wgk     = (const float*)d_in[8];
    const float* bgk     = (const float*)d_in[9];
    const float* wq_conv = (const float*)d_in[10];
    const float* bq_conv = (const float*)d_in[11];
    const float* wk_conv = (const float*)d_in[12];
    const float* bk_conv = (const float*)d_in[13];
    const float* wv_conv = (const float*)d_in[14];
    const float* bv_conv = (const float*)d_in[15];
    const float* A_log   = (const float*)d_in[16];
    const float* Dp      = (const float*)d_in[17];
    const float* dt_bias = (const float*)d_in[18];
    const float* onorm_w = (const float*)d_in[19];
    float* out = (float*)d_out;

    float* S;
    cudaGetSymbolAddress((void**)&S, g_scratch);
    __half* Hb;
    cudaGetSymbolAddress((void**)&Hb, g_half);

    float* bq  = S + OFF_Q;
    float* bk  = S + OFF_K;
    float* bv  = S + OFF_V;
    float* bg  = S + OFF_G;
    float* bqc = S + OFF_QC;
    float* bkc = S + OFF_KC;
    float* bvc = S + OFF_VC;
    float* bo  = S + OFF_O;
    float* bal = S + OFF_AL;
    float* bbe = S + OFF_BE;

    __half* xh  = Hb + HOFF_X;
    __half* wqh = Hb + HOFF_WQ;
    __half* wkh = Hb + HOFF_WK;
    __half* wvh = Hb + HOFF_WV;
    __half* wgh = Hb + HOFF_WG;
    __half* woh = Hb + HOFF_WO;
    __half* oh  = Hb + HOFF_O;

    static int attr_set = 0;
    if (!attr_set) {
        cudaFuncSetAttribute(gemm_f16<true>, cudaFuncAttributeMaxDynamicSharedMemorySize,
                             GEMM_SMEM);
        cudaFuncSetAttribute(gemm_f16<false>, cudaFuncAttributeMaxDynamicSharedMemorySize,
                             GEMM_SMEM);
        attr_set = 1;
    }

    dim3 gth(NE / 4 / 256, 6);
    to_half<<<gth, 256>>>(x, xh, Wq, wqh, Wk, wkh, Wv, wvh, Wg, wgh, Wo, woh);

    // Fused q/k/v/g projection: B = concat(Wq,Wk,Wv,Wg) (contiguous in g_half),
    // outputs to contiguous bq..bg regions via SPLIT mapping.
    dim3 gproj(64, 16);
    gemm_f16<true><<<gproj, 256, GEMM_SMEM>>>(xh, wqh, bq);

    bproj<<<64, 256>>>(x, Wb, bb, Wgk, bgk, A_log, dt_bias, bal, bbe);

    dim3 gcv(TT * KD / 4 / 256, 3);
    conv_silu<<<gcv, 256>>>(bq, wq_conv, bq_conv, bqc,
                            bk, wk_conv, bk_conv, bkc,
                            bv, wv_conv, bv_conv, bvc);

    dim3 gr(TT * NH / 4, 2);
    rope_l2norm<<<gr, 128>>>(bqc, bkc);

    scan_kernel<<<NH, 128>>>(bqc, bkc, bvc, bal, bbe, bo);

    epilogue<<<TT * NH / 4, 128>>>(bo, bvc, bg, Dp, onorm_w, oh);

    dim3 g16(16, 16);
    gemm_f16<false><<<g16, 256, GEMM_SMEM>>>(oh, woh, out);
}

// round 15
// speedup vs baseline: 1.1525x; 1.0215x over previous
#include <cuda_runtime.h>
#include <cuda_fp16.h>
#include <math.h>
#include <stdint.h>

#define TT 2048
#define HIDD 2048
#define NH 32
#define DH 64
#define KD 2048
#define NE (2048u*2048u)

// fp32 scratch: q,k,v,g, qc,kc,vc, o_scan + alpha/beta
__device__ __align__(16) float g_scratch[8ull*NE + 2ull*TT*NH];
// fp16 scratch: xh, wqh, wkh, wvh, wgh, woh, oh   (wqh..wgh contiguous!)
__device__ __align__(16) __half g_half[7ull*NE];
// rope per-m frequency ratio (invf/scale), computed once per launch
__device__ double g_rope_r[32];

#define OFF_Q  (0ull*NE)
#define OFF_K  (1ull*NE)
#define OFF_V  (2ull*NE)
#define OFF_G  (3ull*NE)
#define OFF_QC (4ull*NE)
#define OFF_KC (5ull*NE)
#define OFF_VC (6ull*NE)
#define OFF_O  (7ull*NE)
#define OFF_AL (8ull*NE)
#define OFF_BE (8ull*NE + (unsigned long long)TT*NH)

#define HOFF_X  (0ull*NE)
#define HOFF_WQ (1ull*NE)
#define HOFF_WK (2ull*NE)
#define HOFF_WV (3ull*NE)
#define HOFF_WG (4ull*NE)
#define HOFF_WO (5ull*NE)
#define HOFF_O  (6ull*NE)

typedef unsigned long long u64;

// ---------------------------------------------------------------------------
// FP16 tensor-core NT GEMM: C[m,n] = sum_k A[m*K+k]*B[n*K+k], fp32 accum.
// Block 128x128, BK=32 halves, 8 warps (4m x 2n) of 32x64, mma.m16n8k16.
// 3-stage cp.async pipeline.  SPLIT=true: bx spans 4 concatenated regions.
// ---------------------------------------------------------------------------
#define GK 2048
#define HTILE_BYTES (128*80)          // 10240 per matrix
#define HSTG (2*HTILE_BYTES)          // 20480 per stage (A+B)
#define NSTAGE 3
#define GEMM_SMEM (3u*HSTG)           // 61440

__device__ __forceinline__ void cp_async16(uint32_t saddr, const void* gptr) {
    asm volatile("cp.async.ca.shared.global [%0], [%1], 16;\n" :: "r"(saddr), "l"(gptr));
}

__device__ __forceinline__ void ldsm4(uint32_t* r, uint32_t addr) {
    asm volatile("ldmatrix.sync.aligned.m8n8.x4.shared.b16 {%0,%1,%2,%3}, [%4];"
                 : "=r"(r[0]), "=r"(r[1]), "=r"(r[2]), "=r"(r[3]) : "r"(addr));
}

__device__ __forceinline__ void mma16(float* c, const uint32_t* a, const uint32_t* b) {
    asm volatile(
        "mma.sync.aligned.m16n8k16.row.col.f32.f16.f16.f32 "
        "{%0,%1,%2,%3},{%4,%5,%6,%7},{%8,%9},{%0,%1,%2,%3};\n"
        : "+f"(c[0]), "+f"(c[1]), "+f"(c[2]), "+f"(c[3])
        : "r"(a[0]), "r"(a[1]), "r"(a[2]), "r"(a[3]), "r"(b[0]), "r"(b[1]));
}

template<bool SPLIT>
__global__ __launch_bounds__(256, 2) void gemm_f16(const __half* __restrict__ A,
                                                   const __half* __restrict__ B,
                                                   float* __restrict__ C) {
    extern __shared__ char dsm[];
    const int tid = threadIdx.x;
    const int warp = tid >> 5, lane = tid & 31;
    const int grp = lane >> 2, tig = lane & 3;
    const int wm = (warp >> 1) * 32, wn = (warp & 1) * 64;
    const int bx = blockIdx.x, by = blockIdx.y;

    const __half* Ag = A + (size_t)(by * 128) * GK;
    const __half* Bg = B + (size_t)(bx * 128) * GK;

    float* Cb;
    int gnb;
    if (SPLIT) {
        Cb = C + (size_t)(bx >> 4) * NE;
        gnb = (bx & 15) * 128;
    } else {
        Cb = C;
        gnb = bx * 128;
    }

    float c[2][8][4];
#pragma unroll
    for (int mi = 0; mi < 2; mi++)
#pragma unroll
        for (int nj = 0; nj < 8; nj++)
#pragma unroll
            for (int r = 0; r < 4; r++) c[mi][nj][r] = 0.f;

    const uint32_t smbase = (uint32_t)__cvta_generic_to_shared(dsm);
    const int NKI = GK / 32;

    const int a_r  = (lane & 7) + ((lane >> 3) & 1) * 8;
    const int a_c8 = ((lane >> 4) & 1) * 8;
    const int b_r  = (lane & 7) + ((lane >> 4) & 1) * 8;
    const int b_c8 = ((lane >> 3) & 1) * 8;

    auto issue = [&](int s, int kt) {
        uint32_t stA = smbase + (uint32_t)(s * HSTG);
        uint32_t stB = stA + HTILE_BYTES;
#pragma unroll
        for (int i = 0; i < 2; i++) {
            int idx = tid + i * 256;      // 0..511
            int r = idx >> 2, ch = idx & 3;
            cp_async16(stA + (uint32_t)(r * 80 + ch * 16),
                       Ag + (size_t)r * GK + kt * 32 + ch * 8);
            cp_async16(stB + (uint32_t)(r * 80 + ch * 16),
                       Bg + (size_t)r * GK + kt * 32 + ch * 8);
        }
        asm volatile("cp.async.commit_group;\n");
    };

    issue(0, 0);
    issue(1, 1);

    for (int kt = 0; kt < NKI; kt++) {
        if (kt + 2 < NKI) {
            issue((kt + 2) % NSTAGE, kt + 2);
            asm volatile("cp.async.wait_group 2;\n");
        } else if (kt + 1 < NKI) {
            asm volatile("cp.async.wait_group 1;\n");
        } else {
            asm volatile("cp.async.wait_group 0;\n");
        }
        __syncthreads();

        const int s = kt % NSTAGE;
        uint32_t stA = smbase + (uint32_t)(s * HSTG);
        uint32_t stB = stA + HTILE_BYTES;

#pragma unroll
        for (int ks = 0; ks < 2; ks++) {
            uint32_t av[2][4], bv[8][2];
#pragma unroll
            for (int mi = 0; mi < 2; mi++) {
                uint32_t addr = stA + (uint32_t)((wm + mi * 16 + a_r) * 80
                                                 + (ks * 16 + a_c8) * 2);
                ldsm4(av[mi], addr);
            }
#pragma unroll
            for (int njp = 0; njp < 4; njp++) {
                uint32_t r4[4];
                uint32_t addr = stB + (uint32_t)((wn + njp * 16 + b_r) * 80
                                                 + (ks * 16 + b_c8) * 2);
                ldsm4(r4, addr);
                bv[njp * 2][0] = r4[0]; bv[njp * 2][1] = r4[1];
                bv[njp * 2 + 1][0] = r4[2]; bv[njp * 2 + 1][1] = r4[3];
            }
#pragma unroll
            for (int mi = 0; mi < 2; mi++)
#pragma unroll
                for (int nj = 0; nj < 8; nj++)
                    mma16(c[mi][nj], av[mi], bv[nj]);
        }
        __syncthreads();
    }

#pragma unroll
    for (int mi = 0; mi < 2; mi++) {
        const int gm = by * 128 + wm + mi * 16 + grp;
#pragma unroll
        for (int nj = 0; nj < 8; nj++) {
            const int gn = gnb + wn + nj * 8 + 2 * tig;
            *(float2*)(Cb + (size_t)gm * 2048 + gn) = make_float2(c[mi][nj][0], c[mi][nj][1]);
            *(float2*)(Cb + (size_t)(gm + 8) * 2048 + gn) = make_float2(c[mi][nj][2], c[mi][nj][3]);
        }
    }
}

// ---------------------------------------------------------------------------
// fp32 -> fp16 conversion of x + 5 weight matrices.
// ---------------------------------------------------------------------------
__global__ __launch_bounds__(256) void to_half(const float* __restrict__ s0, __half* __restrict__ d0,
                                               const float* __restrict__ s1, __half* __restrict__ d1,
                                               const float* __restrict__ s2, __half* __restrict__ d2,
                                               const float* __restrict__ s3, __half* __restrict__ d3,
                                               const float* __restrict__ s4, __half* __restrict__ d4,
                                               const float* __restrict__ s5, __half* __restrict__ d5) {
    const float* s; __half* d;
    switch (blockIdx.y) {
        case 0: s = s0; d = d0; break;
        case 1: s = s1; d = d1; break;
        case 2: s = s2; d = d2; break;
        case 3: s = s3; d = d3; break;
        case 4: s = s4; d = d4; break;
        default: s = s5; d = d5; break;
    }
    unsigned i = blockIdx.x * 256u + threadIdx.x;
    float4 v = ((const float4*)s)[i];
    __half2 lo = __floats2half2_rn(v.x, v.y);
    __half2 hi = __floats2half2_rn(v.z, v.w);
    ((__half2*)d)[2 * i] = lo;
    ((__half2*)d)[2 * i + 1] = hi;
}

// ---------------------------------------------------------------------------
// Causal depthwise conv (K=4) + SiLU, 4 timesteps per thread.
// ---------------------------------------------------------------------------
__global__ __launch_bounds__(256) void conv_silu(const float* __restrict__ in0,
                                                 const float* __restrict__ w0,
                                                 const float* __restrict__ b0,
                                                 float* __restrict__ out0,
                                                 const float* __restrict__ in1,
                                                 const float* __restrict__ w1,
                                                 const float* __restrict__ b1,
                                                 float* __restrict__ out1,
                                                 const float* __restrict__ in2,
                                                 const float* __restrict__ w2,
                                                 const float* __restrict__ b2,
                                                 float* __restrict__ out2) {
    const float *in, *w, *b; float* out;
    switch (blockIdx.y) {
        case 0: in = in0; w = w0; b = b0; out = out0; break;
        case 1: in = in1; w = w1; b = b1; out = out1; break;
        default: in = in2; w = w2; b = b2; out = out2; break;
    }
    unsigned idx = blockIdx.x * 256u + threadIdx.x;
    int c = idx & (KD - 1);
    int t0 = (int)(idx >> 11) * 4;
    float4 w4 = ((const float4*)w)[c];
    float bias = b[c];

    const float* p = in + (size_t)t0 * KD + c;
    float xm3, xm2, xm1;
    if (t0 == 0) {
        xm3 = 0.f; xm2 = 0.f; xm1 = 0.f;
    } else {
        xm3 = p[-3 * (int)KD]; xm2 = p[-2 * (int)KD]; xm1 = p[-(int)KD];
    }
    float x0 = p[0];
    float x1 = p[KD];
    float x2 = p[2 * KD];
    float x3 = p[3 * KD];

    float y0 = bias + xm3 * w4.x + xm2 * w4.y + xm1 * w4.z + x0 * w4.w;
    float y1 = bias + xm2 * w4.x + xm1 * w4.y + x0  * w4.z + x1 * w4.w;
    float y2 = bias + xm1 * w4.x + x0  * w4.y + x1  * w4.z + x2 * w4.w;
    float y3 = bias + x0  * w4.x + x1  * w4.y + x2  * w4.z + x3 * w4.w;

    float* q = out + (size_t)t0 * KD + c;
    q[0]      = y0 / (1.f + expf(-y0));
    q[KD]     = y1 / (1.f + expf(-y1));
    q[2 * KD] = y2 / (1.f + expf(-y2));
    q[3 * KD] = y3 / (1.f + expf(-y3));
}

// ---------------------------------------------------------------------------
// beta/alpha via tiled fp32 mini-GEMM (exact fp32; feeds the scan).
// ---------------------------------------------------------------------------
__global__ __launch_bounds__(256) void bproj(const float* __restrict__ x,
                                             const float* __restrict__ Wb,
                                             const float* __restrict__ bb,
                                             const float* __restrict__ Wgk,
                                             const float* __restrict__ bgk,
                                             const float* __restrict__ A_log,
                                             const float* __restrict__ dt_bias,
                                             float* __restrict__ alpha,
                                             float* __restrict__ beta) {
    __shared__ __align__(16) float xs[32][33];
    __shared__ __align__(16) float ws[64][33];
    const int tid = threadIdx.x;
    const int t0 = blockIdx.x * 32;
    const int tn = tid & 15, tt = tid >> 4;
    const int tr = (tt & 15) * 2;
    const int nc = tn * 4;

    float acc[2][4];
#pragma unroll
    for (int i = 0; i < 2; i++)
#pragma unroll
        for (int j = 0; j < 4; j++) acc[i][j] = 0.f;

    for (int k0 = 0; k0 < HIDD; k0 += 32) {
        {
            int row = tid >> 3, kc = (tid & 7) * 4;
            float4 v4 = *(const float4*)&x[(size_t)(t0 + row) * HIDD + k0 + kc];
            xs[row][kc] = v4.x; xs[row][kc + 1] = v4.y;
            xs[row][kc + 2] = v4.z; xs[row][kc + 3] = v4.w;
        }
#pragma unroll
        for (int r = 0; r < 2; r++) {
            int idx = tid + r * 256;
            int n = idx >> 3, kc = (idx & 7) * 4;
            const float* src = (n < 32) ? &Wb[(size_t)n * HIDD + k0 + kc]
                                        : &Wgk[(size_t)(n - 32) * HIDD + k0 + kc];
            float4 v4 = *(const float4*)src;
            ws[n][kc] = v4.x; ws[n][kc + 1] = v4.y;
            ws[n][kc + 2] = v4.z; ws[n][kc + 3] = v4.w;
        }
        __syncthreads();
#pragma unroll
        for (int kk = 0; kk < 32; kk++) {
            float xa0 = xs[tr][kk], xa1 = xs[tr + 1][kk];
            float w0 = ws[nc][kk], w1 = ws[nc + 1][kk];
            float w2 = ws[nc + 2][kk], w3 = ws[nc + 3][kk];
            acc[0][0] += xa0 * w0; acc[0][1] += xa0 * w1;
            acc[0][2] += xa0 * w2; acc[0][3] += xa0 * w3;
            acc[1][0] += xa1 * w0; acc[1][1] += xa1 * w1;
            acc[1][2] += xa1 * w2; acc[1][3] += xa1 * w3;
        }
        __syncthreads();
    }

#pragma unroll
    for (int i = 0; i < 2; i++) {
        int t = t0 + tr + i;
#pragma unroll
        for (int j = 0; j < 4; j++) {
            int n = nc + j;
            if (n < 32) {
                beta[t * NH + n] = 1.f / (1.f + expf(-(acc[i][j] + bb[n])));
            } else {
                int h = n - 32;
                float z = acc[i][j] + bgk[h] + dt_bias[h];
                float sp = fmaxf(z, 0.f) + log1pf(expf(-fabsf(z)));
                alpha[t * NH + h] = expf(-expf(A_log[h]) * sp);
            }
        }
    }
}

// ---------------------------------------------------------------------------
// Rope frequency precompute (once per launch, 32 threads, all DP here).
// ---------------------------------------------------------------------------
__global__ void rope_init() {
    int m = threadIdx.x;   // 0..31
    double invf = pow(10000.0, -((double)(2 * m) / 64.0));
    double wl = 6.283185307179586 / invf;
    double ramp = (wl - 1.0) / 31.0;
    ramp = ramp < 0.0 ? 0.0 : (ramp > 1.0 ? 1.0 : ramp);
    double scale = 1.0 + 31.0 * ramp;
    g_rope_r[m] = invf / scale;
}

// ---------------------------------------------------------------------------
// YaRN RoPE + l2norm, in-place (DP pow hoisted to rope_init).
// ---------------------------------------------------------------------------
__global__ __launch_bounds__(128) void rope_l2norm(float* __restrict__ q,
                                                   float* __restrict__ k) {
    int gw = blockIdx.x * 4 + (threadIdx.x >> 5);
    int lane = threadIdx.x & 31;
    int t = gw >> 5;
    int h = gw & 31;
    float* base = (blockIdx.y == 0 ? q : k) + (size_t)t * KD + h * DH;

    int m = (2 * lane) & 31;
    float f = (float)((double)t * g_rope_r[m]);
    float s, c;
    sincosf(f, &s, &c);

    float x1 = base[2 * lane];
    float x2 = base[2 * lane + 1];
    __syncwarp();
    float lo = x1 * c - x2 * s;
    float hi = x1 * s + x2 * c;
    float ss = lo * lo + hi * hi;
#pragma unroll
    for (int off = 16; off; off >>= 1) ss += __shfl_xor_sync(0xffffffffu, ss, off);
    float r = rsqrtf(ss + 1e-6f);
    base[lane] = lo * r;
    base[lane + 32] = hi * r;
}

// ---------------------------------------------------------------------------
// Sequential delta-rule scan (packed f32x2). One block per head; 128 threads.
// R11/R13 structure (frozen); k/q loaded via float4 (LDS.128) and packed.
// ---------------------------------------------------------------------------
__device__ __forceinline__ u64 pk2(float lo, float hi) {
    u64 r; asm("mov.b64 %0,{%1,%2};" : "=l"(r) : "f"(lo), "f"(hi)); return r;
}
__device__ __forceinline__ void up2(u64 v, float& lo, float& hi) {
    asm("mov.b64 {%0,%1},%2;" : "=f"(lo), "=f"(hi) : "l"(v));
}
__device__ __forceinline__ u64 fma2(u64 a, u64 b, u64 c) {
    u64 d; asm("fma.rn.f32x2 %0,%1,%2,%3;" : "=l"(d) : "l"(a), "l"(b), "l"(c)); return d;
}
__device__ __forceinline__ u64 mul2(u64 a, u64 b) {
    u64 d; asm("mul.rn.f32x2 %0,%1,%2;" : "=l"(d) : "l"(a), "l"(b)); return d;
}

#define CH 32
__global__ __launch_bounds__(128) void scan_kernel(const float* __restrict__ q,
                                                   const float* __restrict__ k,
                                                   const float* __restrict__ v,
                                                   const float* __restrict__ alpha,
                                                   const float* __restrict__ beta,
                                                   float* __restrict__ o) {
    int h = blockIdx.x;
    __shared__ __align__(16) float sq[CH][DH];
    __shared__ __align__(16) float sk[CH][DH];
    __shared__ __align__(16) float sv[CH][DH];
    __shared__ __align__(16) float so[CH][DH];
    __shared__ float sa[CH], sb2[CH];

    int tid = threadIdx.x;
    int j = tid >> 1;
    int hf = tid & 1;
    int base = hf * 32;

    u64 S2[16];
#pragma unroll
    for (int i = 0; i < 16; i++) S2[i] = 0ull;

    for (int t0 = 0; t0 < TT; t0 += CH) {
#pragma unroll
        for (int r = 0; r < 4; r++) {
            int fi = tid + r * 128;
            int s = fi >> 4;
            int d4 = fi & 15;
            size_t gidx = (size_t)(t0 + s) * KD + h * DH + d4 * 4;
            ((float4*)sq[s])[d4] = *(const float4*)&q[gidx];
            ((float4*)sk[s])[d4] = *(const float4*)&k[gidx];
            ((float4*)sv[s])[d4] = *(const float4*)&v[gidx];
        }
        if (tid < CH) {
            sa[tid]  = alpha[(t0 + tid) * NH + h];
            sb2[tid] = beta[(t0 + tid) * NH + h];
        }
        __syncthreads();

        for (int s = 0; s < CH; s++) {
            // float4 (LDS.128) loads of k,q; pack adjacent pairs to u64.
            const float4* kf = (const float4*)&sk[s][base];
            const float4* qf = (const float4*)&sq[s][base];
            u64 kk[16], qq[16];
#pragma unroll
            for (int ii = 0; ii < 8; ii++) {
                float4 kv = kf[ii];
                kk[2 * ii]     = pk2(kv.x, kv.y);
                kk[2 * ii + 1] = pk2(kv.z, kv.w);
                float4 qv = qf[ii];
                qq[2 * ii]     = pk2(qv.x, qv.y);
                qq[2 * ii + 1] = pk2(qv.z, qv.w);
            }

            u64 e0 = 0ull, e1 = 0ull, e2 = 0ull, e3 = 0ull;
#pragma unroll
            for (int ii = 0; ii < 16; ii += 4) {
                e0 = fma2(kk[ii],     S2[ii],     e0);
                e1 = fma2(kk[ii + 1], S2[ii + 1], e1);
                e2 = fma2(kk[ii + 2], S2[ii + 2], e2);
                e3 = fma2(kk[ii + 3], S2[ii + 3], e3);
            }
            float l0, h0, l1, h1, l2, h2, l3, h3;
            up2(e0, l0, h0); up2(e1, l1, h1); up2(e2, l2, h2); up2(e3, l3, h3);
            float errdot = ((l0 + h0) + (l1 + h1)) + ((l2 + h2) + (l3 + h3));
            errdot += __shfl_xor_sync(0xffffffffu, errdot, 1);
            float a = sa[s];
            float u = sb2[s] * (sv[s][j] - a * errdot);
            u64 ab = pk2(a, a), ub = pk2(u, u);
            u64 o0 = 0ull, o1 = 0ull, o2 = 0ull, o3 = 0ull;
#pragma unroll
            for (int ii = 0; ii < 16; ii += 4) {
                S2[ii]     = fma2(kk[ii],     ub, mul2(ab, S2[ii]));
                S2[ii + 1] = fma2(kk[ii + 1], ub, mul2(ab, S2[ii + 1]));
                S2[ii + 2] = fma2(kk[ii + 2], ub, mul2(ab, S2[ii + 2]));
                S2[ii + 3] = fma2(kk[ii + 3], ub, mul2(ab, S2[ii + 3]));
                o0 = fma2(qq[ii],     S2[ii],     o0);
                o1 = fma2(qq[ii + 1], S2[ii + 1], o1);
                o2 = fma2(qq[ii + 2], S2[ii + 2], o2);
                o3 = fma2(qq[ii + 3], S2[ii + 3], o3);
            }
            up2(o0, l0, h0); up2(o1, l1, h1); up2(o2, l2, h2); up2(o3, l3, h3);
            float ov = ((l0 + h0) + (l1 + h1)) + ((l2 + h2) + (l3 + h3));
            ov += __shfl_xor_sync(0xffffffffu, ov, 1);
            if (hf == 0) so[s][j] = ov;
        }
        __syncthreads();
#pragma unroll
        for (int r = 0; r < 4; r++) {
            int fi = tid + r * 128;
            int s = fi >> 4;
            int d4 = fi & 15;
            *(float4*)&o[(size_t)(t0 + s) * KD + h * DH + d4 * 4] = ((float4*)so[s])[d4];
        }
    }
}

// ---------------------------------------------------------------------------
// Epilogue: o = o_scan + D[h]*v; RMS-norm; out = gate * silu(onw * xn).
// ---------------------------------------------------------------------------
__global__ __launch_bounds__(128) void epilogue(const float* __restrict__ o_scan,
                                                const float* __restrict__ v,
                                                const float* __restrict__ gate,
                                                const float* __restrict__ D,
                                                const float* __restrict__ onw,
                                                __half* __restrict__ out) {
    int gw = blockIdx.x * 4 + (threadIdx.x >> 5);
    int lane = threadIdx.x & 31;
    int t = gw >> 5, h = gw & 31;
    size_t base = (size_t)t * KD + h * DH;
    float d = D[h];
    float o0 = o_scan[base + lane]      + d * v[base + lane];
    float o1 = o_scan[base + lane + 32] + d * v[base + lane + 32];
    float ss = o0 * o0 + o1 * o1;
#pragma unroll
    for (int off = 16; off; off >>= 1) ss += __shfl_xor_sync(0xffffffffu, ss, off);
    float r = rsqrtf(ss * (1.f / 64.f) + 1e-6f);
    float z0 = onw[lane]      * o0 * r;
    float z1 = onw[lane + 32] * o1 * r;
    out[base + lane]      = __float2half_rn(gate[base + lane]      * z0 / (1.f + expf(-z0)));
    out[base + lane + 32] = __float2half_rn(gate[base + lane + 32] * z1 / (1.f + expf(-z1)));
}

// ---------------------------------------------------------------------------
extern "C" void kernel_launch(void* const* d_in, const int* in_sizes, int n_in,
                              void* d_out, int out_size) {
    const float* x       = (const float*)d_in[0];
    const float* Wq      = (const float*)d_in[1];
    const float* Wk      = (const float*)d_in[2];
    const float* Wv      = (const float*)d_in[3];
    const float* Wg      = (const float*)d_in[4];
    const float* Wo      = (const float*)d_in[5];
    const float* Wb      = (const float*)d_in[6];
    const float* bb      = (const float*)d_in[7];
    const float* Wgk     = (const float*)d_in[8];
    const float* bgk     = (const float*)d_in[9];
    const float* wq_conv = (const float*)d_in[10];
    const float* bq_conv = (const float*)d_in[11];
    const float* wk_conv = (const float*)d_in[12];
    const float* bk_conv = (const float*)d_in[13];
    const float* wv_conv = (const float*)d_in[14];
    const float* bv_conv = (const float*)d_in[15];
    const float* A_log   = (const float*)d_in[16];
    const float* Dp      = (const float*)d_in[17];
    const float* dt_bias = (const float*)d_in[18];
    const float* onorm_w = (const float*)d_in[19];
    float* out = (float*)d_out;

    float* S;
    cudaGetSymbolAddress((void**)&S, g_scratch);
    __half* Hb;
    cudaGetSymbolAddress((void**)&Hb, g_half);

    float* bq  = S + OFF_Q;
    float* bk  = S + OFF_K;
    float* bv  = S + OFF_V;
    float* bg  = S + OFF_G;
    float* bqc = S + OFF_QC;
    float* bkc = S + OFF_KC;
    float* bvc = S + OFF_VC;
    float* bo  = S + OFF_O;
    float* bal = S + OFF_AL;
    float* bbe = S + OFF_BE;

    __half* xh  = Hb + HOFF_X;
    __half* wqh = Hb + HOFF_WQ;
    __half* woh = Hb + HOFF_WO;
    __half* oh  = Hb + HOFF_O;
    __half* wkh = Hb + HOFF_WK;
    __half* wvh = Hb + HOFF_WV;
    __half* wgh = Hb + HOFF_WG;

    static int attr_set = 0;
    if (!attr_set) {
        cudaFuncSetAttribute(gemm_f16<true>, cudaFuncAttributeMaxDynamicSharedMemorySize,
                             GEMM_SMEM);
        cudaFuncSetAttribute(gemm_f16<false>, cudaFuncAttributeMaxDynamicSharedMemorySize,
                             GEMM_SMEM);
        attr_set = 1;
    }

    rope_init<<<1, 32>>>();

    dim3 gth(NE / 4 / 256, 6);
    to_half<<<gth, 256>>>(x, xh, Wq, wqh, Wk, wkh, Wv, wvh, Wg, wgh, Wo, woh);

    // Fused q/k/v/g projection: B = concat(Wq,Wk,Wv,Wg) contiguous in g_half.
    dim3 gproj(64, 16);
    gemm_f16<true><<<gproj, 256, GEMM_SMEM>>>(xh, wqh, bq);

    bproj<<<64, 256>>>(x, Wb, bb, Wgk, bgk, A_log, dt_bias, bal, bbe);

    dim3 gcv(TT * KD / 4 / 256, 3);
    conv_silu<<<gcv, 256>>>(bq, wq_conv, bq_conv, bqc,
                            bk, wk_conv, bk_conv, bkc,
                            bv, wv_conv, bv_conv, bvc);

    dim3 gr(TT * NH / 4, 2);
    rope_l2norm<<<gr, 128>>>(bqc, bkc);

    scan_kernel<<<NH, 128>>>(bqc, bkc, bvc, bal, bbe, bo);

    epilogue<<<TT * NH / 4, 128>>>(bo, bvc, bg, Dp, onorm_w, oh);

    dim3 g16(16, 16);
    gemm_f16<false><<<g16, 256, GEMM_SMEM>>>(oh, woh, out);
}

// round 16
// speedup vs baseline: 1.2342x; 1.0709x over previous
#include <cuda_runtime.h>
#include <cuda_fp16.h>
#include <math.h>
#include <stdint.h>

#define TT 2048
#define HIDD 2048
#define NH 32
#define DH 64
#define KD 2048
#define NE (2048u*2048u)

// fp32 scratch: q,k,v,g, qc,kc,vc, o_scan + alpha/beta + bproj partials
__device__ __align__(16) float g_scratch[8ull*NE + 2ull*TT*NH + 8ull*TT*64];
// fp16 scratch: xh, wqh, wkh, wvh, wgh, woh, oh   (wqh..wgh contiguous!)
__device__ __align__(16) __half g_half[7ull*NE];
// rope per-m frequency ratio (invf/scale), computed once per launch
__device__ double g_rope_r[32];

#define OFF_Q  (0ull*NE)
#define OFF_K  (1ull*NE)
#define OFF_V  (2ull*NE)
#define OFF_G  (3ull*NE)
#define OFF_QC (4ull*NE)
#define OFF_KC (5ull*NE)
#define OFF_VC (6ull*NE)
#define OFF_O  (7ull*NE)
#define OFF_AL (8ull*NE)
#define OFF_BE (8ull*NE + (unsigned long long)TT*NH)
#define OFF_BP (8ull*NE + 2ull*TT*NH)

#define HOFF_X  (0ull*NE)
#define HOFF_WQ (1ull*NE)
#define HOFF_WK (2ull*NE)
#define HOFF_WV (3ull*NE)
#define HOFF_WG (4ull*NE)
#define HOFF_WO (5ull*NE)
#define HOFF_O  (6ull*NE)

typedef unsigned long long u64;

// ---------------------------------------------------------------------------
// FP16 tensor-core NT GEMM: C[m,n] = sum_k A[m*K+k]*B[n*K+k], fp32 accum.
// Block 128x128, BK=32 halves, 8 warps (4m x 2n) of 32x64, mma.m16n8k16.
// 3-stage cp.async pipeline.  SPLIT=true: bx spans 4 concatenated regions.
// ---------------------------------------------------------------------------
#define GK 2048
#define HTILE_BYTES (128*80)
#define HSTG (2*HTILE_BYTES)
#define NSTAGE 3
#define GEMM_SMEM (3u*HSTG)

__device__ __forceinline__ void cp_async16(uint32_t saddr, const void* gptr) {
    asm volatile("cp.async.ca.shared.global [%0], [%1], 16;\n" :: "r"(saddr), "l"(gptr));
}

__device__ __forceinline__ void ldsm4(uint32_t* r, uint32_t addr) {
    asm volatile("ldmatrix.sync.aligned.m8n8.x4.shared.b16 {%0,%1,%2,%3}, [%4];"
                 : "=r"(r[0]), "=r"(r[1]), "=r"(r[2]), "=r"(r[3]) : "r"(addr));
}

__device__ __forceinline__ void mma16(float* c, const uint32_t* a, const uint32_t* b) {
    asm volatile(
        "mma.sync.aligned.m16n8k16.row.col.f32.f16.f16.f32 "
        "{%0,%1,%2,%3},{%4,%5,%6,%7},{%8,%9},{%0,%1,%2,%3};\n"
        : "+f"(c[0]), "+f"(c[1]), "+f"(c[2]), "+f"(c[3])
        : "r"(a[0]), "r"(a[1]), "r"(a[2]), "r"(a[3]), "r"(b[0]), "r"(b[1]));
}

template<bool SPLIT>
__global__ __launch_bounds__(256, 2) void gemm_f16(const __half* __restrict__ A,
                                                   const __half* __restrict__ B,
                                                   float* __restrict__ C) {
    extern __shared__ char dsm[];
    const int tid = threadIdx.x;
    const int warp = tid >> 5, lane = tid & 31;
    const int grp = lane >> 2, tig = lane & 3;
    const int wm = (warp >> 1) * 32, wn = (warp & 1) * 64;
    const int bx = blockIdx.x, by = blockIdx.y;

    const __half* Ag = A + (size_t)(by * 128) * GK;
    const __half* Bg = B + (size_t)(bx * 128) * GK;

    float* Cb;
    int gnb;
    if (SPLIT) {
        Cb = C + (size_t)(bx >> 4) * NE;
        gnb = (bx & 15) * 128;
    } else {
        Cb = C;
        gnb = bx * 128;
    }

    float c[2][8][4];
#pragma unroll
    for (int mi = 0; mi < 2; mi++)
#pragma unroll
        for (int nj = 0; nj < 8; nj++)
#pragma unroll
            for (int r = 0; r < 4; r++) c[mi][nj][r] = 0.f;

    const uint32_t smbase = (uint32_t)__cvta_generic_to_shared(dsm);
    const int NKI = GK / 32;

    const int a_r  = (lane & 7) + ((lane >> 3) & 1) * 8;
    const int a_c8 = ((lane >> 4) & 1) * 8;
    const int b_r  = (lane & 7) + ((lane >> 4) & 1) * 8;
    const int b_c8 = ((lane >> 3) & 1) * 8;

    auto issue = [&](int s, int kt) {
        uint32_t stA = smbase + (uint32_t)(s * HSTG);
        uint32_t stB = stA + HTILE_BYTES;
#pragma unroll
        for (int i = 0; i < 2; i++) {
            int idx = tid + i * 256;
            int r = idx >> 2, ch = idx & 3;
            cp_async16(stA + (uint32_t)(r * 80 + ch * 16),
                       Ag + (size_t)r * GK + kt * 32 + ch * 8);
            cp_async16(stB + (uint32_t)(r * 80 + ch * 16),
                       Bg + (size_t)r * GK + kt * 32 + ch * 8);
        }
        asm volatile("cp.async.commit_group;\n");
    };

    issue(0, 0);
    issue(1, 1);

    for (int kt = 0; kt < NKI; kt++) {
        if (kt + 2 < NKI) {
            issue((kt + 2) % NSTAGE, kt + 2);
            asm volatile("cp.async.wait_group 2;\n");
        } else if (kt + 1 < NKI) {
            asm volatile("cp.async.wait_group 1;\n");
        } else {
            asm volatile("cp.async.wait_group 0;\n");
        }
        __syncthreads();

        const int s = kt % NSTAGE;
        uint32_t stA = smbase + (uint32_t)(s * HSTG);
        uint32_t stB = stA + HTILE_BYTES;

#pragma unroll
        for (int ks = 0; ks < 2; ks++) {
            uint32_t av[2][4], bv[8][2];
#pragma unroll
            for (int mi = 0; mi < 2; mi++) {
                uint32_t addr = stA + (uint32_t)((wm + mi * 16 + a_r) * 80
                                                 + (ks * 16 + a_c8) * 2);
                ldsm4(av[mi], addr);
            }
#pragma unroll
            for (int njp = 0; njp < 4; njp++) {
                uint32_t r4[4];
                uint32_t addr = stB + (uint32_t)((wn + njp * 16 + b_r) * 80
                                                 + (ks * 16 + b_c8) * 2);
                ldsm4(r4, addr);
                bv[njp * 2][0] = r4[0]; bv[njp * 2][1] = r4[1];
                bv[njp * 2 + 1][0] = r4[2]; bv[njp * 2 + 1][1] = r4[3];
            }
#pragma unroll
            for (int mi = 0; mi < 2; mi++)
#pragma unroll
                for (int nj = 0; nj < 8; nj++)
                    mma16(c[mi][nj], av[mi], bv[nj]);
        }
        __syncthreads();
    }

#pragma unroll
    for (int mi = 0; mi < 2; mi++) {
        const int gm = by * 128 + wm + mi * 16 + grp;
#pragma unroll
        for (int nj = 0; nj < 8; nj++) {
            const int gn = gnb + wn + nj * 8 + 2 * tig;
            *(float2*)(Cb + (size_t)gm * 2048 + gn) = make_float2(c[mi][nj][0], c[mi][nj][1]);
            *(float2*)(Cb + (size_t)(gm + 8) * 2048 + gn) = make_float2(c[mi][nj][2], c[mi][nj][3]);
        }
    }
}

// ---------------------------------------------------------------------------
// fp32 -> fp16 conversion of x + 5 weight matrices.
// ---------------------------------------------------------------------------
__global__ __launch_bounds__(256) void to_half(const float* __restrict__ s0, __half* __restrict__ d0,
                                               const float* __restrict__ s1, __half* __restrict__ d1,
                                               const float* __restrict__ s2, __half* __restrict__ d2,
                                               const float* __restrict__ s3, __half* __restrict__ d3,
                                               const float* __restrict__ s4, __half* __restrict__ d4,
                                               const float* __restrict__ s5, __half* __restrict__ d5) {
    const float* s; __half* d;
    switch (blockIdx.y) {
        case 0: s = s0; d = d0; break;
        case 1: s = s1; d = d1; break;
        case 2: s = s2; d = d2; break;
        case 3: s = s3; d = d3; break;
        case 4: s = s4; d = d4; break;
        default: s = s5; d = d5; break;
    }
    unsigned i = blockIdx.x * 256u + threadIdx.x;
    float4 v = ((const float4*)s)[i];
    __half2 lo = __floats2half2_rn(v.x, v.y);
    __half2 hi = __floats2half2_rn(v.z, v.w);
    ((__half2*)d)[2 * i] = lo;
    ((__half2*)d)[2 * i + 1] = hi;
}

// ---------------------------------------------------------------------------
// Causal depthwise conv (K=4) + SiLU, 4 timesteps per thread.
// ---------------------------------------------------------------------------
__global__ __launch_bounds__(256) void conv_silu(const float* __restrict__ in0,
                                                 const float* __restrict__ w0,
                                                 const float* __restrict__ b0,
                                                 float* __restrict__ out0,
                                                 const float* __restrict__ in1,
                                                 const float* __restrict__ w1,
                                                 const float* __restrict__ b1,
                                                 float* __restrict__ out1,
                                                 const float* __restrict__ in2,
                                                 const float* __restrict__ w2,
                                                 const float* __restrict__ b2,
                                                 float* __restrict__ out2) {
    const float *in, *w, *b; float* out;
    switch (blockIdx.y) {
        case 0: in = in0; w = w0; b = b0; out = out0; break;
        case 1: in = in1; w = w1; b = b1; out = out1; break;
        default: in = in2; w = w2; b = b2; out = out2; break;
    }
    unsigned idx = blockIdx.x * 256u + threadIdx.x;
    int c = idx & (KD - 1);
    int t0 = (int)(idx >> 11) * 4;
    float4 w4 = ((const float4*)w)[c];
    float bias = b[c];

    const float* p = in + (size_t)t0 * KD + c;
    float xm3, xm2, xm1;
    if (t0 == 0) {
        xm3 = 0.f; xm2 = 0.f; xm1 = 0.f;
    } else {
        xm3 = p[-3 * (int)KD]; xm2 = p[-2 * (int)KD]; xm1 = p[-(int)KD];
    }
    float x0 = p[0];
    float x1 = p[KD];
    float x2 = p[2 * KD];
    float x3 = p[3 * KD];

    float y0 = bias + xm3 * w4.x + xm2 * w4.y + xm1 * w4.z + x0 * w4.w;
    float y1 = bias + xm2 * w4.x + xm1 * w4.y + x0  * w4.z + x1 * w4.w;
    float y2 = bias + xm1 * w4.x + x0  * w4.y + x1  * w4.z + x2 * w4.w;
    float y3 = bias + x0  * w4.x + x1  * w4.y + x2  * w4.z + x3 * w4.w;

    float* q = out + (size_t)t0 * KD + c;
    q[0]      = y0 / (1.f + expf(-y0));
    q[KD]     = y1 / (1.f + expf(-y1));
    q[2 * KD] = y2 / (1.f + expf(-y2));
    q[3 * KD] = y3 / (1.f + expf(-y3));
}

// ---------------------------------------------------------------------------
// beta/alpha projection, K-split: grid (64 t-blocks, 8 k-blocks).
// Each block reduces a K=256 slice; partials to scratch; finalize sums
// in fixed kb order (deterministic) and applies nonlinearities.
// ---------------------------------------------------------------------------
__global__ __launch_bounds__(256) void bproj_part(const float* __restrict__ x,
                                                  const float* __restrict__ Wb,
                                                  const float* __restrict__ Wgk,
                                                  float* __restrict__ partial) {
    __shared__ __align__(16) float xs[32][33];
    __shared__ __align__(16) float ws[64][33];
    const int tid = threadIdx.x;
    const int t0 = blockIdx.x * 32;
    const int kb = blockIdx.y;
    const int tn = tid & 15, tt = tid >> 4;
    const int tr = (tt & 15) * 2;
    const int nc = tn * 4;

    float acc[2][4];
#pragma unroll
    for (int i = 0; i < 2; i++)
#pragma unroll
        for (int j = 0; j < 4; j++) acc[i][j] = 0.f;

    for (int k0 = kb * 256; k0 < kb * 256 + 256; k0 += 32) {
        {
            int row = tid >> 3, kc = (tid & 7) * 4;
            float4 v4 = *(const float4*)&x[(size_t)(t0 + row) * HIDD + k0 + kc];
            xs[row][kc] = v4.x; xs[row][kc + 1] = v4.y;
            xs[row][kc + 2] = v4.z; xs[row][kc + 3] = v4.w;
        }
#pragma unroll
        for (int r = 0; r < 2; r++) {
            int idx = tid + r * 256;
            int n = idx >> 3, kc = (idx & 7) * 4;
            const float* src = (n < 32) ? &Wb[(size_t)n * HIDD + k0 + kc]
                                        : &Wgk[(size_t)(n - 32) * HIDD + k0 + kc];
            float4 v4 = *(const float4*)src;
            ws[n][kc] = v4.x; ws[n][kc + 1] = v4.y;
            ws[n][kc + 2] = v4.z; ws[n][kc + 3] = v4.w;
        }
        __syncthreads();
#pragma unroll
        for (int kk = 0; kk < 32; kk++) {
            float xa0 = xs[tr][kk], xa1 = xs[tr + 1][kk];
            float w0 = ws[nc][kk], w1 = ws[nc + 1][kk];
            float w2 = ws[nc + 2][kk], w3 = ws[nc + 3][kk];
            acc[0][0] += xa0 * w0; acc[0][1] += xa0 * w1;
            acc[0][2] += xa0 * w2; acc[0][3] += xa0 * w3;
            acc[1][0] += xa1 * w0; acc[1][1] += xa1 * w1;
            acc[1][2] += xa1 * w2; acc[1][3] += xa1 * w3;
        }
        __syncthreads();
    }

    float* pb = partial + (size_t)kb * TT * 64;
#pragma unroll
    for (int i = 0; i < 2; i++) {
        int t = t0 + tr + i;
#pragma unroll
        for (int j = 0; j < 4; j++)
            pb[(size_t)t * 64 + nc + j] = acc[i][j];
    }
}

__global__ __launch_bounds__(256) void bproj_final(const float* __restrict__ partial,
                                                   const float* __restrict__ bb,
                                                   const float* __restrict__ bgk,
                                                   const float* __restrict__ A_log,
                                                   const float* __restrict__ dt_bias,
                                                   float* __restrict__ alpha,
                                                   float* __restrict__ beta) {
    unsigned idx = blockIdx.x * 256u + threadIdx.x;   // 0 .. TT*64-1
    int t = idx >> 6;
    int n = idx & 63;
    float s = 0.f;
#pragma unroll
    for (int kb = 0; kb < 8; kb++)
        s += partial[(size_t)kb * TT * 64 + idx];
    if (n < 32) {
        beta[t * NH + n] = 1.f / (1.f + expf(-(s + bb[n])));
    } else {
        int h = n - 32;
        float z = s + bgk[h] + dt_bias[h];
        float sp = fmaxf(z, 0.f) + log1pf(expf(-fabsf(z)));
        alpha[t * NH + h] = expf(-expf(A_log[h]) * sp);
    }
}

// ---------------------------------------------------------------------------
// Rope frequency precompute (once per launch, 32 threads, all DP here).
// ---------------------------------------------------------------------------
__global__ void rope_init() {
    int m = threadIdx.x;
    double invf = pow(10000.0, -((double)(2 * m) / 64.0));
    double wl = 6.283185307179586 / invf;
    double ramp = (wl - 1.0) / 31.0;
    ramp = ramp < 0.0 ? 0.0 : (ramp > 1.0 ? 1.0 : ramp);
    double scale = 1.0 + 31.0 * ramp;
    g_rope_r[m] = invf / scale;
}

// ---------------------------------------------------------------------------
// YaRN RoPE + l2norm, in-place (DP pow hoisted to rope_init).
// ---------------------------------------------------------------------------
__global__ __launch_bounds__(128) void rope_l2norm(float* __restrict__ q,
                                                   float* __restrict__ k) {
    int gw = blockIdx.x * 4 + (threadIdx.x >> 5);
    int lane = threadIdx.x & 31;
    int t = gw >> 5;
    int h = gw & 31;
    float* base = (blockIdx.y == 0 ? q : k) + (size_t)t * KD + h * DH;

    int m = (2 * lane) & 31;
    float f = (float)((double)t * g_rope_r[m]);
    float s, c;
    sincosf(f, &s, &c);

    float x1 = base[2 * lane];
    float x2 = base[2 * lane + 1];
    __syncwarp();
    float lo = x1 * c - x2 * s;
    float hi = x1 * s + x2 * c;
    float ss = lo * lo + hi * hi;
#pragma unroll
    for (int off = 16; off; off >>= 1) ss += __shfl_xor_sync(0xffffffffu, ss, off);
    float r = rsqrtf(ss + 1e-6f);
    base[lane] = lo * r;
    base[lane + 32] = hi * r;
}

// ---------------------------------------------------------------------------
// Sequential delta-rule scan (packed f32x2). One block per head; 128 threads.
// R11/R13 structure (frozen); k/q loaded via float4 (LDS.128) and packed.
// ---------------------------------------------------------------------------
__device__ __forceinline__ u64 pk2(float lo, float hi) {
    u64 r; asm("mov.b64 %0,{%1,%2};" : "=l"(r) : "f"(lo), "f"(hi)); return r;
}
__device__ __forceinline__ void up2(u64 v, float& lo, float& hi) {
    asm("mov.b64 {%0,%1},%2;" : "=f"(lo), "=f"(hi) : "l"(v));
}
__device__ __forceinline__ u64 fma2(u64 a, u64 b, u64 c) {
    u64 d; asm("fma.rn.f32x2 %0,%1,%2,%3;" : "=l"(d) : "l"(a), "l"(b), "l"(c)); return d;
}
__device__ __forceinline__ u64 mul2(u64 a, u64 b) {
    u64 d; asm("mul.rn.f32x2 %0,%1,%2;" : "=l"(d) : "l"(a), "l"(b)); return d;
}

#define CH 32
__global__ __launch_bounds__(128) void scan_kernel(const float* __restrict__ q,
                                                   const float* __restrict__ k,
                                                   const float* __restrict__ v,
                                                   const float* __restrict__ alpha,
                                                   const float* __restrict__ beta,
                                                   float* __restrict__ o) {
    int h = blockIdx.x;
    __shared__ __align__(16) float sq[CH][DH];
    __shared__ __align__(16) float sk[CH][DH];
    __shared__ __align__(16) float sv[CH][DH];
    __shared__ __align__(16) float so[CH][DH];
    __shared__ float sa[CH], sb2[CH];

    int tid = threadIdx.x;
    int j = tid >> 1;
    int hf = tid & 1;
    int base = hf * 32;

    u64 S2[16];
#pragma unroll
    for (int i = 0; i < 16; i++) S2[i] = 0ull;

    for (int t0 = 0; t0 < TT; t0 += CH) {
#pragma unroll
        for (int r = 0; r < 4; r++) {
            int fi = tid + r * 128;
            int s = fi >> 4;
            int d4 = fi & 15;
            size_t gidx = (size_t)(t0 + s) * KD + h * DH + d4 * 4;
            ((float4*)sq[s])[d4] = *(const float4*)&q[gidx];
            ((float4*)sk[s])[d4] = *(const float4*)&k[gidx];
            ((float4*)sv[s])[d4] = *(const float4*)&v[gidx];
        }
        if (tid < CH) {
            sa[tid]  = alpha[(t0 + tid) * NH + h];
            sb2[tid] = beta[(t0 + tid) * NH + h];
        }
        __syncthreads();

        for (int s = 0; s < CH; s++) {
            const float4* kf = (const float4*)&sk[s][base];
            const float4* qf = (const float4*)&sq[s][base];
            u64 kk[16], qq[16];
#pragma unroll
            for (int ii = 0; ii < 8; ii++) {
                float4 kv = kf[ii];
                kk[2 * ii]     = pk2(kv.x, kv.y);
                kk[2 * ii + 1] = pk2(kv.z, kv.w);
                float4 qv = qf[ii];
                qq[2 * ii]     = pk2(qv.x, qv.y);
                qq[2 * ii + 1] = pk2(qv.z, qv.w);
            }

            u64 e0 = 0ull, e1 = 0ull, e2 = 0ull, e3 = 0ull;
#pragma unroll
            for (int ii = 0; ii < 16; ii += 4) {
                e0 = fma2(kk[ii],     S2[ii],     e0);
                e1 = fma2(kk[ii + 1], S2[ii + 1], e1);
                e2 = fma2(kk[ii + 2], S2[ii + 2], e2);
                e3 = fma2(kk[ii + 3], S2[ii + 3], e3);
            }
            float l0, h0, l1, h1, l2, h2, l3, h3;
            up2(e0, l0, h0); up2(e1, l1, h1); up2(e2, l2, h2); up2(e3, l3, h3);
            float errdot = ((l0 + h0) + (l1 + h1)) + ((l2 + h2) + (l3 + h3));
            errdot += __shfl_xor_sync(0xffffffffu, errdot, 1);
            float a = sa[s];
            float u = sb2[s] * (sv[s][j] - a * errdot);
            u64 ab = pk2(a, a), ub = pk2(u, u);
            u64 o0 = 0ull, o1 = 0ull, o2 = 0ull, o3 = 0ull;
#pragma unroll
            for (int ii = 0; ii < 16; ii += 4) {
                S2[ii]     = fma2(kk[ii],     ub, mul2(ab, S2[ii]));
                S2[ii + 1] = fma2(kk[ii + 1], ub, mul2(ab, S2[ii + 1]));
                S2[ii + 2] = fma2(kk[ii + 2], ub, mul2(ab, S2[ii + 2]));
                S2[ii + 3] = fma2(kk[ii + 3], ub, mul2(ab, S2[ii + 3]));
                o0 = fma2(qq[ii],     S2[ii],     o0);
                o1 = fma2(qq[ii + 1], S2[ii + 1], o1);
                o2 = fma2(qq[ii + 2], S2[ii + 2], o2);
                o3 = fma2(qq[ii + 3], S2[ii + 3], o3);
            }
            up2(o0, l0, h0); up2(o1, l1, h1); up2(o2, l2, h2); up2(o3, l3, h3);
            float ov = ((l0 + h0) + (l1 + h1)) + ((l2 + h2) + (l3 + h3));
            ov += __shfl_xor_sync(0xffffffffu, ov, 1);
            if (hf == 0) so[s][j] = ov;
        }
        __syncthreads();
#pragma unroll
        for (int r = 0; r < 4; r++) {
            int fi = tid + r * 128;
            int s = fi >> 4;
            int d4 = fi & 15;
            *(float4*)&o[(size_t)(t0 + s) * KD + h * DH + d4 * 4] = ((float4*)so[s])[d4];
        }
    }
}

// ---------------------------------------------------------------------------
// Epilogue: o = o_scan + D[h]*v; RMS-norm; out = gate * silu(onw * xn).
// ---------------------------------------------------------------------------
__global__ __launch_bounds__(128) void epilogue(const float* __restrict__ o_scan,
                                                const float* __restrict__ v,
                                                const float* __restrict__ gate,
                                                const float* __restrict__ D,
                                                const float* __restrict__ onw,
                                                __half* __restrict__ out) {
    int gw = blockIdx.x * 4 + (threadIdx.x >> 5);
    int lane = threadIdx.x & 31;
    int t = gw >> 5, h = gw & 31;
    size_t base = (size_t)t * KD + h * DH;
    float d = D[h];
    float o0 = o_scan[base + lane]      + d * v[base + lane];
    float o1 = o_scan[base + lane + 32] + d * v[base + lane + 32];
    float ss = o0 * o0 + o1 * o1;
#pragma unroll
    for (int off = 16; off; off >>= 1) ss += __shfl_xor_sync(0xffffffffu, ss, off);
    float r = rsqrtf(ss * (1.f / 64.f) + 1e-6f);
    float z0 = onw[lane]      * o0 * r;
    float z1 = onw[lane + 32] * o1 * r;
    out[base + lane]      = __float2half_rn(gate[base + lane]      * z0 / (1.f + expf(-z0)));
    out[base + lane + 32] = __float2half_rn(gate[base + lane + 32] * z1 / (1.f + expf(-z1)));
}

// ---------------------------------------------------------------------------
extern "C" void kernel_launch(void* const* d_in, const int* in_sizes, int n_in,
                              void* d_out, int out_size) {
    const float* x       = (const float*)d_in[0];
    const float* Wq      = (const float*)d_in[1];
    const float* Wk      = (const float*)d_in[2];
    const float* Wv      = (const float*)d_in[3];
    const float* Wg      = (const float*)d_in[4];
    const float* Wo      = (const float*)d_in[5];
    const float* Wb      = (const float*)d_in[6];
    const float* bb      = (const float*)d_in[7];
    const float* Wgk     = (const float*)d_in[8];
    const float* bgk     = (const float*)d_in[9];
    const float* wq_conv = (const float*)d_in[10];
    const float* bq_conv = (const float*)d_in[11];
    const float* wk_conv = (const float*)d_in[12];
    const float* bk_conv = (const float*)d_in[13];
    const float* wv_conv = (const float*)d_in[14];
    const float* bv_conv = (const float*)d_in[15];
    const float* A_log   = (const float*)d_in[16];
    const float* Dp      = (const float*)d_in[17];
    const float* dt_bias = (const float*)d_in[18];
    const float* onorm_w = (const float*)d_in[19];
    float* out = (float*)d_out;

    float* S;
    cudaGetSymbolAddress((void**)&S, g_scratch);
    __half* Hb;
    cudaGetSymbolAddress((void**)&Hb, g_half);

    float* bq  = S + OFF_Q;
    float* bk  = S + OFF_K;
    float* bv  = S + OFF_V;
    float* bg  = S + OFF_G;
    float* bqc = S + OFF_QC;
    float* bkc = S + OFF_KC;
    float* bvc = S + OFF_VC;
    float* bo  = S + OFF_O;
    float* bal = S + OFF_AL;
    float* bbe = S + OFF_BE;
    float* bpp = S + OFF_BP;

    __half* xh  = Hb + HOFF_X;
    __half* wqh = Hb + HOFF_WQ;
    __half* wkh = Hb + HOFF_WK;
    __half* wvh = Hb + HOFF_WV;
    __half* wgh = Hb + HOFF_WG;
    __half* woh = Hb + HOFF_WO;
    __half* oh  = Hb + HOFF_O;

    static int attr_set = 0;
    if (!attr_set) {
        cudaFuncSetAttribute(gemm_f16<true>, cudaFuncAttributeMaxDynamicSharedMemorySize,
                             GEMM_SMEM);
        cudaFuncSetAttribute(gemm_f16<false>, cudaFuncAttributeMaxDynamicSharedMemorySize,
                             GEMM_SMEM);
        attr_set = 1;
    }

    rope_init<<<1, 32>>>();

    dim3 gth(NE / 4 / 256, 6);
    to_half<<<gth, 256>>>(x, xh, Wq, wqh, Wk, wkh, Wv, wvh, Wg, wgh, Wo, woh);

    dim3 gproj(64, 16);
    gemm_f16<true><<<gproj, 256, GEMM_SMEM>>>(xh, wqh, bq);

    dim3 gbp(64, 8);
    bproj_part<<<gbp, 256>>>(x, Wb, Wgk, bpp);
    bproj_final<<<TT * 64 / 256, 256>>>(bpp, bb, bgk, A_log, dt_bias, bal, bbe);

    dim3 gcv(TT * KD / 4 / 256, 3);
    conv_silu<<<gcv, 256>>>(bq, wq_conv, bq_conv, bqc,
                            bk, wk_conv, bk_conv, bkc,
                            bv, wv_conv, bv_conv, bvc);

    dim3 gr(TT * NH / 4, 2);
    rope_l2norm<<<gr, 128>>>(bqc, bkc);

    scan_kernel<<<NH, 128>>>(bqc, bkc, bvc, bal, bbe, bo);

    epilogue<<<TT * NH / 4, 128>>>(bo, bvc, bg, Dp, onorm_w, oh);

    dim3 g16(16, 16);
    gemm_f16<false><<<g16, 256, GEMM_SMEM>>>(oh, woh, out);
}